// round 9
// baseline (speedup 1.0000x reference)
#include <cuda_runtime.h>

#define BB 4
#define TT 2048
#define CC 1024
#define HS 64
#define KSPLIT 4
#define SCALE 0.03125f   // C^-0.5 = 1024^-0.5

typedef unsigned long long u64;

// ---- packed f32x2 helpers (sm_100+ PTX) -----------------------------------
__device__ __forceinline__ u64 pk1(float x) {
    u64 r; asm("mov.b64 %0,{%1,%1};" : "=l"(r) : "f"(x)); return r;
}
__device__ __forceinline__ void fma2(u64& d, u64 a, u64 b) {
    asm("fma.rn.f32x2 %0,%1,%2,%0;" : "+l"(d) : "l"(a), "l"(b));
}
__device__ __forceinline__ void mul2(u64& d, u64 a) {
    asm("mul.rn.f32x2 %0,%0,%1;" : "+l"(d) : "l"(a));
}
__device__ __forceinline__ void upk(u64 v, float& lo, float& hi) {
    asm("mov.b64 {%0,%1},%2;" : "=f"(lo), "=f"(hi) : "l"(v));
}
__device__ __forceinline__ u64 swp(u64 v) {
    u64 r;
    asm("{\n\t.reg .b32 lo,hi;\n\tmov.b64 {lo,hi},%1;\n\tmov.b64 %0,{hi,lo};\n\t}"
        : "=l"(r) : "l"(v));
    return r;
}

// Scratch (static device allocations; no cudaMalloc allowed)
__device__ float g_q[BB * TT * HS];
__device__ float g_k[BB * TT * HS];
__device__ float g_v[BB * TT * HS];
__device__ float g_p2[3 * BB * TT * HS];    // qkv K-split second-half partials
__device__ float g_pacc[(size_t)BB * KSPLIT * TT * HS];
__device__ float g_pm[BB * KSPLIT * TT];
__device__ float g_pl[BB * KSPLIT * TT];

// ---------------------------------------------------------------------------
// Kernel 1: QKV projection with K-split (unchanged from best config).
// grid = (128 row-tiles, 3 matrices, 2 k-halves), 256 threads, BM=BN=64, BK=32.
// Diagonal/cross FFMA2 micro-kernel.
// ---------------------------------------------------------------------------
__global__ __launch_bounds__(256) void qkv_kernel(
    const float* __restrict__ x,
    const float* __restrict__ Wq,
    const float* __restrict__ Wk,
    const float* __restrict__ Wv) {
    const int m = blockIdx.y;
    const float* W = (m == 0) ? Wq : (m == 1) ? Wk : Wv;
    float* out = (blockIdx.z == 0)
        ? ((m == 0) ? g_q : (m == 1) ? g_k : g_v)
        : &g_p2[(size_t)m * BB * TT * HS];

    __shared__ float Xs[32][68];   // [k][row], padded stride
    __shared__ float Ws[32][64];   // [k][col]

    const int tid = threadIdx.x;
    const int tx = tid & 15;
    const int ty = tid >> 4;
    const int row0 = blockIdx.x * 64;
    const int kbase = blockIdx.z * (CC / 2);

    const int lrow = tid >> 2;     // 0..63
    const int lq   = tid & 3;      // 0..3
    const int wk   = tid >> 3;     // 0..31
    const int wf   = tid & 7;      // 0..7

    u64 aD[2][2] = {}, aX[2][2] = {};

    float4 px0, px1, pw0, pw1;
    {   // prefetch chunk 0
        const int k0 = kbase;
        px0 = *reinterpret_cast<const float4*>(
            &x[(size_t)(row0 + lrow) * CC + k0 + lq * 4]);
        px1 = *reinterpret_cast<const float4*>(
            &x[(size_t)(row0 + lrow) * CC + k0 + (lq + 4) * 4]);
        pw0 = *reinterpret_cast<const float4*>(&W[(size_t)(k0 + wk) * HS + wf * 4]);
        pw1 = *reinterpret_cast<const float4*>(&W[(size_t)(k0 + wk) * HS + (wf + 8) * 4]);
    }

    for (int c = 0; c < 16; c++) {
        {
            int f0 = lq, f1 = lq + 4;
            Xs[f0 * 4 + 0][lrow] = px0.x;
            Xs[f0 * 4 + 1][lrow] = px0.y;
            Xs[f0 * 4 + 2][lrow] = px0.z;
            Xs[f0 * 4 + 3][lrow] = px0.w;
            Xs[f1 * 4 + 0][lrow] = px1.x;
            Xs[f1 * 4 + 1][lrow] = px1.y;
            Xs[f1 * 4 + 2][lrow] = px1.z;
            Xs[f1 * 4 + 3][lrow] = px1.w;
            *reinterpret_cast<float4*>(&Ws[wk][wf * 4]) = pw0;
            *reinterpret_cast<float4*>(&Ws[wk][(wf + 8) * 4]) = pw1;
        }
        __syncthreads();

        if (c < 15) {
            const int k0 = kbase + (c + 1) * 32;
            px0 = *reinterpret_cast<const float4*>(
                &x[(size_t)(row0 + lrow) * CC + k0 + lq * 4]);
            px1 = *reinterpret_cast<const float4*>(
                &x[(size_t)(row0 + lrow) * CC + k0 + (lq + 4) * 4]);
            pw0 = *reinterpret_cast<const float4*>(
                &W[(size_t)(k0 + wk) * HS + wf * 4]);
            pw1 = *reinterpret_cast<const float4*>(
                &W[(size_t)(k0 + wk) * HS + (wf + 8) * 4]);
        }

#pragma unroll
        for (int kk = 0; kk < 32; kk++) {
            ulonglong2 av = *reinterpret_cast<ulonglong2*>(&Xs[kk][ty * 4]);
            ulonglong2 bv = *reinterpret_cast<ulonglong2*>(&Ws[kk][tx * 4]);
            u64 s0 = swp(bv.x), s1 = swp(bv.y);
            fma2(aD[0][0], av.x, bv.x); fma2(aD[0][1], av.x, bv.y);
            fma2(aX[0][0], av.x, s0);   fma2(aX[0][1], av.x, s1);
            fma2(aD[1][0], av.y, bv.x); fma2(aD[1][1], av.y, bv.y);
            fma2(aX[1][0], av.y, s0);   fma2(aX[1][1], av.y, s1);
        }
        __syncthreads();
    }

    float o[4][4];
#pragma unroll
    for (int p = 0; p < 2; p++)
#pragma unroll
        for (int q = 0; q < 2; q++) {
            float dlo, dhi, xlo, xhi;
            upk(aD[p][q], dlo, dhi);
            upk(aX[p][q], xlo, xhi);
            o[2 * p][2 * q]         = dlo;
            o[2 * p + 1][2 * q + 1] = dhi;
            o[2 * p][2 * q + 1]     = xlo;
            o[2 * p + 1][2 * q]     = xhi;
        }
#pragma unroll
    for (int i = 0; i < 4; i++) {
        *reinterpret_cast<float4*>(
            &out[(size_t)(row0 + ty * 4 + i) * HS + tx * 4]) =
            make_float4(o[i][0], o[i][1], o[i][2], o[i][3]);
    }
}

// ---------------------------------------------------------------------------
// Kernel 1b: merge the two K-halves
// ---------------------------------------------------------------------------
__global__ __launch_bounds__(256) void qkv_add_kernel() {
    const int f4 = blockIdx.x * 256 + threadIdx.x;
    const int per = (BB * TT * HS) / 4;
    const int m = f4 / per;
    const int i = f4 - m * per;
    float* g = (m == 0) ? g_q : (m == 1) ? g_k : g_v;
    float4 a = *reinterpret_cast<float4*>(&g[i * 4]);
    float4 b = *reinterpret_cast<const float4*>(
        &g_p2[(size_t)m * BB * TT * HS + i * 4]);
    a.x += b.x; a.y += b.y; a.z += b.z; a.w += b.w;
    *reinterpret_cast<float4*>(&g[i * 4]) = a;
}

// ---------------------------------------------------------------------------
// Kernel 2: flash-attention partials, key-split now KSPLIT=4.
// grid = (32 q-tiles, 4 splits, 4 batches) = 512 blocks, 128 threads.
// ---------------------------------------------------------------------------
__global__ __launch_bounds__(128) void attn_partial_kernel() {
    const int qtile = blockIdx.x;
    const int split = blockIdx.y;
    const int b     = blockIdx.z;

    const int tid = threadIdx.x;
    const int tx = tid & 15;
    const int ty = tid >> 4;
    const int r0 = ty * 8;
    const int c0 = tx * 4;

    __shared__ float Qt[64][64];   // [h][row], pre-scaled
    __shared__ float KP[64][64];   // K: [h][key]; reused as P: [row][key]
    __shared__ float Vs[64][64];   // [key][dim]

    const int q0 = qtile * 64;
    const int lrow = tid >> 1;
    const int lh   = tid & 1;

#pragma unroll
    for (int i = 0; i < 8; i++) {
        int f = lh + 2 * i;
        float4 qv = *reinterpret_cast<const float4*>(
            &g_q[(size_t)(b * TT + q0 + lrow) * HS + f * 4]);
        Qt[f * 4 + 0][lrow] = qv.x * SCALE;
        Qt[f * 4 + 1][lrow] = qv.y * SCALE;
        Qt[f * 4 + 2][lrow] = qv.z * SCALE;
        Qt[f * 4 + 3][lrow] = qv.w * SCALE;
    }

    float m_[8], l_[8];
    u64 acc[8][2] = {};
#pragma unroll
    for (int i = 0; i < 8; i++) { m_[i] = -1e30f; l_[i] = 0.f; }

    for (int kt = split; kt <= qtile; kt += KSPLIT) {
        const int k0 = kt * 64;
        __syncthreads();

#pragma unroll
        for (int i = 0; i < 8; i++) {
            int f = lh + 2 * i;
            float4 kv = *reinterpret_cast<const float4*>(
                &g_k[(size_t)(b * TT + k0 + lrow) * HS + f * 4]);
            KP[f * 4 + 0][lrow] = kv.x;
            KP[f * 4 + 1][lrow] = kv.y;
            KP[f * 4 + 2][lrow] = kv.z;
            KP[f * 4 + 3][lrow] = kv.w;
            *reinterpret_cast<float4*>(&Vs[lrow][f * 4]) =
                *reinterpret_cast<const float4*>(
                    &g_v[(size_t)(b * TT + k0 + lrow) * HS + f * 4]);
        }
        __syncthreads();

        // S = (Q*scale) K^T, diag/cross form
        u64 sD[4][2] = {}, sX[4][2] = {};
#pragma unroll 16
        for (int h = 0; h < 64; h++) {
            ulonglong2 aA = *reinterpret_cast<ulonglong2*>(&Qt[h][r0]);
            ulonglong2 aB = *reinterpret_cast<ulonglong2*>(&Qt[h][r0 + 4]);
            ulonglong2 bV = *reinterpret_cast<ulonglong2*>(&KP[h][c0]);
            u64 s0 = swp(bV.x), s1 = swp(bV.y);
            fma2(sD[0][0], aA.x, bV.x); fma2(sD[0][1], aA.x, bV.y);
            fma2(sX[0][0], aA.x, s0);   fma2(sX[0][1], aA.x, s1);
            fma2(sD[1][0], aA.y, bV.x); fma2(sD[1][1], aA.y, bV.y);
            fma2(sX[1][0], aA.y, s0);   fma2(sX[1][1], aA.y, s1);
            fma2(sD[2][0], aB.x, bV.x); fma2(sD[2][1], aB.x, bV.y);
            fma2(sX[2][0], aB.x, s0);   fma2(sX[2][1], aB.x, s1);
            fma2(sD[3][0], aB.y, bV.x); fma2(sD[3][1], aB.y, bV.y);
            fma2(sX[3][0], aB.y, s0);   fma2(sX[3][1], aB.y, s1);
        }

        float s[8][4];
#pragma unroll
        for (int rp = 0; rp < 4; rp++)
#pragma unroll
            for (int q = 0; q < 2; q++) {
                float dlo, dhi, xlo, xhi;
                upk(sD[rp][q], dlo, dhi);
                upk(sX[rp][q], xlo, xhi);
                s[2 * rp][2 * q]         = dlo;
                s[2 * rp + 1][2 * q + 1] = dhi;
                s[2 * rp][2 * q + 1]     = xlo;
                s[2 * rp + 1][2 * q]     = xhi;
            }

        if (kt == qtile) {
#pragma unroll
            for (int i = 0; i < 8; i++)
#pragma unroll
                for (int j = 0; j < 4; j++)
                    if (c0 + j > r0 + i) s[i][j] = -1e30f;
        }

#pragma unroll
        for (int i = 0; i < 8; i++) {
            float tm = fmaxf(fmaxf(s[i][0], s[i][1]), fmaxf(s[i][2], s[i][3]));
#pragma unroll
            for (int o = 1; o < 16; o <<= 1)
                tm = fmaxf(tm, __shfl_xor_sync(0xffffffffu, tm, o));
            float nm  = fmaxf(m_[i], tm);
            float cor = __expf(m_[i] - nm);
            float rs = 0.f;
#pragma unroll
            for (int j = 0; j < 4; j++) {
                s[i][j] = __expf(s[i][j] - nm);
                rs += s[i][j];
            }
#pragma unroll
            for (int o = 1; o < 16; o <<= 1)
                rs += __shfl_xor_sync(0xffffffffu, rs, o);
            l_[i] = l_[i] * cor + rs;
            m_[i] = nm;
            u64 corp = pk1(cor);
            mul2(acc[i][0], corp);
            mul2(acc[i][1], corp);
        }

        __syncthreads();
#pragma unroll
        for (int i = 0; i < 8; i++) {
            *reinterpret_cast<float4*>(&KP[r0 + i][c0]) =
                make_float4(s[i][0], s[i][1], s[i][2], s[i][3]);
        }
        __syncthreads();

#pragma unroll
        for (int j4 = 0; j4 < 16; j4++) {
            ulonglong2 w0 = *reinterpret_cast<ulonglong2*>(&Vs[j4 * 4 + 0][c0]);
            ulonglong2 w1 = *reinterpret_cast<ulonglong2*>(&Vs[j4 * 4 + 1][c0]);
            ulonglong2 w2 = *reinterpret_cast<ulonglong2*>(&Vs[j4 * 4 + 2][c0]);
            ulonglong2 w3 = *reinterpret_cast<ulonglong2*>(&Vs[j4 * 4 + 3][c0]);
#pragma unroll
            for (int i = 0; i < 8; i++) {
                float4 p = *reinterpret_cast<float4*>(&KP[r0 + i][j4 * 4]);
                u64 px = pk1(p.x), py = pk1(p.y), pz = pk1(p.z), pw = pk1(p.w);
                fma2(acc[i][0], px, w0.x); fma2(acc[i][1], px, w0.y);
                fma2(acc[i][0], py, w1.x); fma2(acc[i][1], py, w1.y);
                fma2(acc[i][0], pz, w2.x); fma2(acc[i][1], pz, w2.y);
                fma2(acc[i][0], pw, w3.x); fma2(acc[i][1], pw, w3.y);
            }
        }
    }

    const size_t base = (size_t)(b * KSPLIT + split) * TT + q0;
#pragma unroll
    for (int i = 0; i < 8; i++) {
        int r = r0 + i;
        *reinterpret_cast<ulonglong2*>(&g_pacc[(base + r) * HS + c0]) =
            make_ulonglong2(acc[i][0], acc[i][1]);
        if (tx == 0) {
            g_pm[base + r] = m_[i];
            g_pl[base + r] = l_[i];
        }
    }
}

// ---------------------------------------------------------------------------
// Kernel 3: combine split partials (KSPLIT=4 now — half the traffic).
// ---------------------------------------------------------------------------
__global__ __launch_bounds__(256) void combine_kernel(float* __restrict__ out) {
    const int idx = blockIdx.x * 256 + threadIdx.x;
    const int d   = idx & (HS - 1);
    const int row = idx >> 6;
    const int b   = row >> 11;
    const int q   = row & (TT - 1);

    float M = -1e30f;
#pragma unroll
    for (int s = 0; s < KSPLIT; s++)
        M = fmaxf(M, g_pm[(size_t)(b * KSPLIT + s) * TT + q]);

    float L = 0.f, A = 0.f;
#pragma unroll
    for (int s = 0; s < KSPLIT; s++) {
        size_t pb = (size_t)(b * KSPLIT + s) * TT + q;
        float w = __expf(g_pm[pb] - M);
        L += g_pl[pb] * w;
        A += g_pacc[pb * HS + d] * w;
    }
    out[idx] = A / L;
}

// ---------------------------------------------------------------------------
extern "C" void kernel_launch(void* const* d_in, const int* in_sizes, int n_in,
                              void* d_out, int out_size) {
    const float* x  = (const float*)d_in[0];
    const float* Wq = (const float*)d_in[1];
    const float* Wk = (const float*)d_in[2];
    const float* Wv = (const float*)d_in[3];
    float* out = (float*)d_out;

    qkv_kernel<<<dim3((BB * TT) / 64, 3, 2), 256>>>(x, Wq, Wk, Wv);
    qkv_add_kernel<<<(3 * BB * TT * HS / 4) / 256, 256>>>();
    attn_partial_kernel<<<dim3(TT / 64, KSPLIT, BB), 128>>>();
    combine_kernel<<<(BB * TT * HS) / 256, 256>>>(out);
}

// round 10
// speedup vs baseline: 1.4197x; 1.4197x over previous
#include <cuda_runtime.h>
#include <cuda_bf16.h>

#define BB 4
#define TT 2048
#define CC 1024
#define HS 64
#define KSPLIT 8
#define SCALE 0.03125f   // C^-0.5 = 1024^-0.5

typedef unsigned long long u64;
typedef unsigned int u32;

// ---- packed f32x2 helpers (attention kernel) ------------------------------
__device__ __forceinline__ u64 pk1(float x) {
    u64 r; asm("mov.b64 %0,{%1,%1};" : "=l"(r) : "f"(x)); return r;
}
__device__ __forceinline__ void fma2(u64& d, u64 a, u64 b) {
    asm("fma.rn.f32x2 %0,%1,%2,%0;" : "+l"(d) : "l"(a), "l"(b));
}
__device__ __forceinline__ void mul2(u64& d, u64 a) {
    asm("mul.rn.f32x2 %0,%0,%1;" : "+l"(d) : "l"(a));
}
__device__ __forceinline__ void upk(u64 v, float& lo, float& hi) {
    asm("mov.b64 {%0,%1},%2;" : "=f"(lo), "=f"(hi) : "l"(v));
}
__device__ __forceinline__ u64 swp(u64 v) {
    u64 r;
    asm("{\n\t.reg .b32 lo,hi;\n\tmov.b64 {lo,hi},%1;\n\tmov.b64 %0,{hi,lo};\n\t}"
        : "=l"(r) : "l"(v));
    return r;
}

// ---- warp-level HMMA: D[16x8] += A[16x16] * B[16x8]  (bf16 in, f32 acc) ----
__device__ __forceinline__ void mma16816(float* d, const u32* a, u32 b0, u32 b1) {
    asm volatile(
        "mma.sync.aligned.m16n8k16.row.col.f32.bf16.bf16.f32 "
        "{%0,%1,%2,%3},{%4,%5,%6,%7},{%8,%9},{%0,%1,%2,%3};"
        : "+f"(d[0]), "+f"(d[1]), "+f"(d[2]), "+f"(d[3])
        : "r"(a[0]), "r"(a[1]), "r"(a[2]), "r"(a[3]), "r"(b0), "r"(b1));
}

__device__ __forceinline__ u32 bfpack(float a, float b) {
    __nv_bfloat162 t = __floats2bfloat162_rn(a, b);
    return *reinterpret_cast<u32*>(&t);
}

// Scratch (static device allocations; no cudaMalloc allowed)
__device__ float g_q[BB * TT * HS];
__device__ float g_k[BB * TT * HS];
__device__ float g_v[BB * TT * HS];
__device__ float g_pacc[(size_t)BB * KSPLIT * TT * HS];
__device__ float g_pm[BB * KSPLIT * TT];
__device__ float g_pl[BB * KSPLIT * TT];
// W transposed + bf16 hi/lo split: [mat][part][n][k]
__device__ __align__(16) __nv_bfloat16 g_wt[3 * 2 * HS * CC];

// ---------------------------------------------------------------------------
// Kernel 0: transpose + split W into bf16 hi/lo.  Writes coalesced over k.
// ---------------------------------------------------------------------------
__global__ __launch_bounds__(256) void wconvert_kernel(
    const float* __restrict__ Wq,
    const float* __restrict__ Wk,
    const float* __restrict__ Wv) {
    int idx = blockIdx.x * 256 + threadIdx.x;          // over 3*64*1024
    int k = idx & (CC - 1);
    int n = (idx >> 10) & (HS - 1);
    int m = idx >> 16;
    const float* W = (m == 0) ? Wq : (m == 1) ? Wk : Wv;
    float v = W[(size_t)k * HS + n];
    __nv_bfloat16 hi = __float2bfloat16_rn(v);
    float lo = v - __bfloat162float(hi);
    size_t base = ((size_t)(m * 2) * HS + n) * CC + k;
    g_wt[base]           = hi;                          // part 0
    g_wt[base + HS * CC] = __float2bfloat16_rn(lo);     // part 1
}

// ---------------------------------------------------------------------------
// Kernel 1: QKV via mma.sync bf16x3.
// grid = 128 (BM=64), 256 threads (8 warps: wm=warp&3 row group, wn=warp>>2
// col half).  BK=32 chunks, register prefetch, padded smem (40 halfs/row)
// for conflict-free fragment LDS.
// ---------------------------------------------------------------------------
__global__ __launch_bounds__(256) void qkv_mma_kernel(const float* __restrict__ x) {
    __shared__ __align__(16) __nv_bfloat16 Xh[64 * 40];
    __shared__ __align__(16) __nv_bfloat16 Xl[64 * 40];
    __shared__ __align__(16) __nv_bfloat16 Wt[6 * 64 * 40];   // [t][n][kpad]

    const int tid  = threadIdx.x;
    const int warp = tid >> 5;
    const int lane = tid & 31;
    const int wm = warp & 3;          // row group (16 rows)
    const int wn = warp >> 2;         // col half (32 cols)
    const int lr  = lane >> 2;        // 0..7
    const int lc2 = (lane & 3) * 2;   // 0,2,4,6
    const int row0 = blockIdx.x * 64;

    const int xrow = tid >> 2;        // 0..63
    const int xq   = tid & 3;         // 0..3  (8 floats each)

    float acc[3][4][4] = {};

    // prefetch registers
    float4 pxa, pxb;
    uint4 pw[6];

    // --- prefetch chunk 0
    {
        const float* s = &x[(size_t)(row0 + xrow) * CC + xq * 8];
        pxa = *reinterpret_cast<const float4*>(s);
        pxb = *reinterpret_cast<const float4*>(s + 4);
#pragma unroll
        for (int u = 0; u < 6; u++) {
            int lin = u * 256 + tid;
            int t = lin >> 8, w = lin & 255;
            int n = w >> 2, kg = w & 3;
            pw[u] = *reinterpret_cast<const uint4*>(
                &g_wt[((size_t)t * HS + n) * CC + kg * 8]);
        }
    }

    for (int c = 0; c < 32; c++) {
        if (c) __syncthreads();

        // --- store prefetched X (split hi/lo) and W
        {
            float v[8] = {pxa.x, pxa.y, pxa.z, pxa.w, pxb.x, pxb.y, pxb.z, pxb.w};
            float h[8], l[8];
#pragma unroll
            for (int e = 0; e < 8; e++) {
                h[e] = __bfloat162float(__float2bfloat16_rn(v[e]));
                l[e] = v[e] - h[e];
            }
            *reinterpret_cast<uint4*>(&Xh[xrow * 40 + xq * 8]) =
                make_uint4(bfpack(h[0], h[1]), bfpack(h[2], h[3]),
                           bfpack(h[4], h[5]), bfpack(h[6], h[7]));
            *reinterpret_cast<uint4*>(&Xl[xrow * 40 + xq * 8]) =
                make_uint4(bfpack(l[0], l[1]), bfpack(l[2], l[3]),
                           bfpack(l[4], l[5]), bfpack(l[6], l[7]));
#pragma unroll
            for (int u = 0; u < 6; u++) {
                int lin = u * 256 + tid;
                int t = lin >> 8, w = lin & 255;
                int n = w >> 2, kg = w & 3;
                *reinterpret_cast<uint4*>(&Wt[t * 2560 + n * 40 + kg * 8]) = pw[u];
            }
        }
        __syncthreads();

        // --- prefetch next chunk (overlaps MMA below)
        if (c < 31) {
            const int kc = (c + 1) * 32;
            const float* s = &x[(size_t)(row0 + xrow) * CC + kc + xq * 8];
            pxa = *reinterpret_cast<const float4*>(s);
            pxb = *reinterpret_cast<const float4*>(s + 4);
#pragma unroll
            for (int u = 0; u < 6; u++) {
                int lin = u * 256 + tid;
                int t = lin >> 8, w = lin & 255;
                int n = w >> 2, kg = w & 3;
                pw[u] = *reinterpret_cast<const uint4*>(
                    &g_wt[((size_t)t * HS + n) * CC + kc + kg * 8]);
            }
        }

        // --- A fragments (2 k-steps x hi/lo)
        u32 Ah[2][4], Al[2][4];
#pragma unroll
        for (int ks = 0; ks < 2; ks++) {
            int k0 = ks * 16;
            int r1 = (wm * 16 + lr) * 40, r2 = r1 + 8 * 40;
            Ah[ks][0] = *reinterpret_cast<u32*>(&Xh[r1 + k0 + lc2]);
            Ah[ks][1] = *reinterpret_cast<u32*>(&Xh[r2 + k0 + lc2]);
            Ah[ks][2] = *reinterpret_cast<u32*>(&Xh[r1 + k0 + lc2 + 8]);
            Ah[ks][3] = *reinterpret_cast<u32*>(&Xh[r2 + k0 + lc2 + 8]);
            Al[ks][0] = *reinterpret_cast<u32*>(&Xl[r1 + k0 + lc2]);
            Al[ks][1] = *reinterpret_cast<u32*>(&Xl[r2 + k0 + lc2]);
            Al[ks][2] = *reinterpret_cast<u32*>(&Xl[r1 + k0 + lc2 + 8]);
            Al[ks][3] = *reinterpret_cast<u32*>(&Xl[r2 + k0 + lc2 + 8]);
        }

        // --- MMAs: 3 mats x 4 n-tiles x 2 k-steps x 3 terms
#pragma unroll
        for (int mat = 0; mat < 3; mat++) {
            const __nv_bfloat16* Wh = &Wt[(mat * 2) * 2560];
            const __nv_bfloat16* Wl = Wh + 2560;
#pragma unroll
            for (int nt = 0; nt < 4; nt++) {
                int nr = (wn * 32 + nt * 8 + lr) * 40;
                float* D = acc[mat][nt];
#pragma unroll
                for (int ks = 0; ks < 2; ks++) {
                    int k0 = ks * 16;
                    u32 bh0 = *reinterpret_cast<const u32*>(&Wh[nr + k0 + lc2]);
                    u32 bh1 = *reinterpret_cast<const u32*>(&Wh[nr + k0 + lc2 + 8]);
                    u32 bl0 = *reinterpret_cast<const u32*>(&Wl[nr + k0 + lc2]);
                    u32 bl1 = *reinterpret_cast<const u32*>(&Wl[nr + k0 + lc2 + 8]);
                    mma16816(D, Ah[ks], bh0, bh1);
                    mma16816(D, Al[ks], bh0, bh1);
                    mma16816(D, Ah[ks], bl0, bl1);
                }
            }
        }
    }

    // --- epilogue
#pragma unroll
    for (int mat = 0; mat < 3; mat++) {
        float* dst = (mat == 0) ? g_q : (mat == 1) ? g_k : g_v;
#pragma unroll
        for (int nt = 0; nt < 4; nt++) {
            int col = wn * 32 + nt * 8 + lc2;
            size_t r = (size_t)(row0 + wm * 16 + lr);
            *reinterpret_cast<float2*>(&dst[r * HS + col]) =
                make_float2(acc[mat][nt][0], acc[mat][nt][1]);
            *reinterpret_cast<float2*>(&dst[(r + 8) * HS + col]) =
                make_float2(acc[mat][nt][2], acc[mat][nt][3]);
        }
    }
}

// ---------------------------------------------------------------------------
// Kernel 2: flash-attention partials with key-split (KSPLIT=8, R6 config).
// grid = (32 q-tiles, 8 splits, 4 batches), 128 threads, BM=BN=64.
// ---------------------------------------------------------------------------
__global__ __launch_bounds__(128) void attn_partial_kernel() {
    const int qtile = blockIdx.x;
    const int split = blockIdx.y;
    const int b     = blockIdx.z;

    const int tid = threadIdx.x;
    const int tx = tid & 15;
    const int ty = tid >> 4;
    const int r0 = ty * 8;
    const int c0 = tx * 4;

    __shared__ float Qt[64][64];   // [h][row], pre-scaled
    __shared__ float KP[64][64];   // K: [h][key]; reused as P: [row][key]
    __shared__ float Vs[64][64];   // [key][dim]

    const int q0 = qtile * 64;
    const int lrow = tid >> 1;
    const int lh   = tid & 1;

#pragma unroll
    for (int i = 0; i < 8; i++) {
        int f = lh + 2 * i;
        float4 qv = *reinterpret_cast<const float4*>(
            &g_q[(size_t)(b * TT + q0 + lrow) * HS + f * 4]);
        Qt[f * 4 + 0][lrow] = qv.x * SCALE;
        Qt[f * 4 + 1][lrow] = qv.y * SCALE;
        Qt[f * 4 + 2][lrow] = qv.z * SCALE;
        Qt[f * 4 + 3][lrow] = qv.w * SCALE;
    }

    float m_[8], l_[8];
    u64 acc[8][2] = {};
#pragma unroll
    for (int i = 0; i < 8; i++) { m_[i] = -1e30f; l_[i] = 0.f; }

    for (int kt = split; kt <= qtile; kt += KSPLIT) {
        const int k0 = kt * 64;
        __syncthreads();

#pragma unroll
        for (int i = 0; i < 8; i++) {
            int f = lh + 2 * i;
            float4 kv = *reinterpret_cast<const float4*>(
                &g_k[(size_t)(b * TT + k0 + lrow) * HS + f * 4]);
            KP[f * 4 + 0][lrow] = kv.x;
            KP[f * 4 + 1][lrow] = kv.y;
            KP[f * 4 + 2][lrow] = kv.z;
            KP[f * 4 + 3][lrow] = kv.w;
            *reinterpret_cast<float4*>(&Vs[lrow][f * 4]) =
                *reinterpret_cast<const float4*>(
                    &g_v[(size_t)(b * TT + k0 + lrow) * HS + f * 4]);
        }
        __syncthreads();

        // S = (Q*scale) K^T, diag/cross FFMA2 form
        u64 sD[4][2] = {}, sX[4][2] = {};
#pragma unroll 16
        for (int h = 0; h < 64; h++) {
            ulonglong2 aA = *reinterpret_cast<ulonglong2*>(&Qt[h][r0]);
            ulonglong2 aB = *reinterpret_cast<ulonglong2*>(&Qt[h][r0 + 4]);
            ulonglong2 bV = *reinterpret_cast<ulonglong2*>(&KP[h][c0]);
            u64 s0 = swp(bV.x), s1 = swp(bV.y);
            fma2(sD[0][0], aA.x, bV.x); fma2(sD[0][1], aA.x, bV.y);
            fma2(sX[0][0], aA.x, s0);   fma2(sX[0][1], aA.x, s1);
            fma2(sD[1][0], aA.y, bV.x); fma2(sD[1][1], aA.y, bV.y);
            fma2(sX[1][0], aA.y, s0);   fma2(sX[1][1], aA.y, s1);
            fma2(sD[2][0], aB.x, bV.x); fma2(sD[2][1], aB.x, bV.y);
            fma2(sX[2][0], aB.x, s0);   fma2(sX[2][1], aB.x, s1);
            fma2(sD[3][0], aB.y, bV.x); fma2(sD[3][1], aB.y, bV.y);
            fma2(sX[3][0], aB.y, s0);   fma2(sX[3][1], aB.y, s1);
        }

        float s[8][4];
#pragma unroll
        for (int rp = 0; rp < 4; rp++)
#pragma unroll
            for (int q = 0; q < 2; q++) {
                float dlo, dhi, xlo, xhi;
                upk(sD[rp][q], dlo, dhi);
                upk(sX[rp][q], xlo, xhi);
                s[2 * rp][2 * q]         = dlo;
                s[2 * rp + 1][2 * q + 1] = dhi;
                s[2 * rp][2 * q + 1]     = xlo;
                s[2 * rp + 1][2 * q]     = xhi;
            }

        if (kt == qtile) {
#pragma unroll
            for (int i = 0; i < 8; i++)
#pragma unroll
                for (int j = 0; j < 4; j++)
                    if (c0 + j > r0 + i) s[i][j] = -1e30f;
        }

#pragma unroll
        for (int i = 0; i < 8; i++) {
            float tm = fmaxf(fmaxf(s[i][0], s[i][1]), fmaxf(s[i][2], s[i][3]));
#pragma unroll
            for (int o = 1; o < 16; o <<= 1)
                tm = fmaxf(tm, __shfl_xor_sync(0xffffffffu, tm, o));
            float nm  = fmaxf(m_[i], tm);
            float cor = __expf(m_[i] - nm);
            float rs = 0.f;
#pragma unroll
            for (int j = 0; j < 4; j++) {
                s[i][j] = __expf(s[i][j] - nm);
                rs += s[i][j];
            }
#pragma unroll
            for (int o = 1; o < 16; o <<= 1)
                rs += __shfl_xor_sync(0xffffffffu, rs, o);
            l_[i] = l_[i] * cor + rs;
            m_[i] = nm;
            u64 corp = pk1(cor);
            mul2(acc[i][0], corp);
            mul2(acc[i][1], corp);
        }

        __syncthreads();
#pragma unroll
        for (int i = 0; i < 8; i++) {
            *reinterpret_cast<float4*>(&KP[r0 + i][c0]) =
                make_float4(s[i][0], s[i][1], s[i][2], s[i][3]);
        }
        __syncthreads();

#pragma unroll
        for (int j4 = 0; j4 < 16; j4++) {
            ulonglong2 w0 = *reinterpret_cast<ulonglong2*>(&Vs[j4 * 4 + 0][c0]);
            ulonglong2 w1 = *reinterpret_cast<ulonglong2*>(&Vs[j4 * 4 + 1][c0]);
            ulonglong2 w2 = *reinterpret_cast<ulonglong2*>(&Vs[j4 * 4 + 2][c0]);
            ulonglong2 w3 = *reinterpret_cast<ulonglong2*>(&Vs[j4 * 4 + 3][c0]);
#pragma unroll
            for (int i = 0; i < 8; i++) {
                float4 p = *reinterpret_cast<float4*>(&KP[r0 + i][j4 * 4]);
                u64 px = pk1(p.x), py = pk1(p.y), pz = pk1(p.z), pw = pk1(p.w);
                fma2(acc[i][0], px, w0.x); fma2(acc[i][1], px, w0.y);
                fma2(acc[i][0], py, w1.x); fma2(acc[i][1], py, w1.y);
                fma2(acc[i][0], pz, w2.x); fma2(acc[i][1], pz, w2.y);
                fma2(acc[i][0], pw, w3.x); fma2(acc[i][1], pw, w3.y);
            }
        }
    }

    const size_t base = (size_t)(b * KSPLIT + split) * TT + q0;
#pragma unroll
    for (int i = 0; i < 8; i++) {
        int r = r0 + i;
        *reinterpret_cast<ulonglong2*>(&g_pacc[(base + r) * HS + c0]) =
            make_ulonglong2(acc[i][0], acc[i][1]);
        if (tx == 0) {
            g_pm[base + r] = m_[i];
            g_pl[base + r] = l_[i];
        }
    }
}

// ---------------------------------------------------------------------------
// Kernel 3: combine split partials into the final output.
// ---------------------------------------------------------------------------
__global__ __launch_bounds__(256) void combine_kernel(float* __restrict__ out) {
    const int idx = blockIdx.x * 256 + threadIdx.x;
    const int d   = idx & (HS - 1);
    const int row = idx >> 6;
    const int b   = row >> 11;
    const int q   = row & (TT - 1);

    float M = -1e30f;
#pragma unroll
    for (int s = 0; s < KSPLIT; s++)
        M = fmaxf(M, g_pm[(size_t)(b * KSPLIT + s) * TT + q]);

    float L = 0.f, A = 0.f;
#pragma unroll
    for (int s = 0; s < KSPLIT; s++) {
        size_t pb = (size_t)(b * KSPLIT + s) * TT + q;
        float w = __expf(g_pm[pb] - M);
        L += g_pl[pb] * w;
        A += g_pacc[pb * HS + d] * w;
    }
    out[idx] = A / L;
}

// ---------------------------------------------------------------------------
extern "C" void kernel_launch(void* const* d_in, const int* in_sizes, int n_in,
                              void* d_out, int out_size) {
    const float* x  = (const float*)d_in[0];
    const float* Wq = (const float*)d_in[1];
    const float* Wk = (const float*)d_in[2];
    const float* Wv = (const float*)d_in[3];
    float* out = (float*)d_out;

    wconvert_kernel<<<(3 * HS * CC) / 256, 256>>>(Wq, Wk, Wv);
    qkv_mma_kernel<<<(BB * TT) / 64, 256>>>(x);
    attn_partial_kernel<<<dim3(TT / 64, KSPLIT, BB), 128>>>();
    combine_kernel<<<(BB * TT * HS) / 256, 256>>>(out);
}

// round 13
// speedup vs baseline: 2.0485x; 1.4429x over previous
#include <cuda_runtime.h>
#include <cuda_bf16.h>

#define BB 4
#define TT 2048
#define CC 1024
#define HS 64
#define KSPLIT 8
#define SCALE 0.03125f   // C^-0.5 = 1024^-0.5

typedef unsigned long long u64;
typedef unsigned int u32;

// ---- warp-level HMMA: D[16x8] += A[16x16] * B[16x8]  (bf16 in, f32 acc) ----
__device__ __forceinline__ void mma16816(float* d, const u32* a, u32 b0, u32 b1) {
    asm volatile(
        "mma.sync.aligned.m16n8k16.row.col.f32.bf16.bf16.f32 "
        "{%0,%1,%2,%3},{%4,%5,%6,%7},{%8,%9},{%0,%1,%2,%3};"
        : "+f"(d[0]), "+f"(d[1]), "+f"(d[2]), "+f"(d[3])
        : "r"(a[0]), "r"(a[1]), "r"(a[2]), "r"(a[3]), "r"(b0), "r"(b1));
}

__device__ __forceinline__ u32 bfpack(float a, float b) {
    __nv_bfloat162 t = __floats2bfloat162_rn(a, b);
    return *reinterpret_cast<u32*>(&t);
}
__device__ __forceinline__ float bfhi(float v) {
    return __bfloat162float(__float2bfloat16_rn(v));
}

// Scratch (static device allocations; no cudaMalloc allowed)
__device__ float g_q[BB * TT * HS];
__device__ float g_k[BB * TT * HS];
__device__ float g_v[BB * TT * HS];
__device__ float g_pacc[(size_t)BB * KSPLIT * TT * HS];
__device__ float g_pm[BB * KSPLIT * TT];
__device__ float g_pl[BB * KSPLIT * TT];
// W transposed + bf16 hi/lo split: [mat][part][n][k]
__device__ __align__(16) __nv_bfloat16 g_wt[3 * 2 * HS * CC];
// attention operands, bf16 hi/lo
__device__ __align__(16) __nv_bfloat16 g_qh[BB * TT * HS];  // pre-scaled
__device__ __align__(16) __nv_bfloat16 g_ql[BB * TT * HS];
__device__ __align__(16) __nv_bfloat16 g_kh[BB * TT * HS];
__device__ __align__(16) __nv_bfloat16 g_kl[BB * TT * HS];
__device__ __align__(16) __nv_bfloat16 g_vth[BB * HS * TT]; // transposed [b][d][t]
__device__ __align__(16) __nv_bfloat16 g_vtl[BB * HS * TT];

// ---------------------------------------------------------------------------
// Kernel 0: transpose + split W into bf16 hi/lo.
// ---------------------------------------------------------------------------
__global__ __launch_bounds__(256) void wconvert_kernel(
    const float* __restrict__ Wq,
    const float* __restrict__ Wk,
    const float* __restrict__ Wv) {
    int idx = blockIdx.x * 256 + threadIdx.x;
    int k = idx & (CC - 1);
    int n = (idx >> 10) & (HS - 1);
    int m = idx >> 16;
    const float* W = (m == 0) ? Wq : (m == 1) ? Wk : Wv;
    float v = W[(size_t)k * HS + n];
    __nv_bfloat16 hi = __float2bfloat16_rn(v);
    float lo = v - __bfloat162float(hi);
    size_t base = ((size_t)(m * 2) * HS + n) * CC + k;
    g_wt[base]           = hi;
    g_wt[base + HS * CC] = __float2bfloat16_rn(lo);
}

// ---------------------------------------------------------------------------
// Kernel 1: QKV via mma.sync bf16x3 (unchanged from R10 WIN).
// ---------------------------------------------------------------------------
__global__ __launch_bounds__(256) void qkv_mma_kernel(const float* __restrict__ x) {
    __shared__ __align__(16) __nv_bfloat16 Xh[64 * 40];
    __shared__ __align__(16) __nv_bfloat16 Xl[64 * 40];
    __shared__ __align__(16) __nv_bfloat16 Wt[6 * 64 * 40];

    const int tid  = threadIdx.x;
    const int warp = tid >> 5;
    const int lane = tid & 31;
    const int wm = warp & 3;
    const int wn = warp >> 2;
    const int lr  = lane >> 2;
    const int lc2 = (lane & 3) * 2;
    const int row0 = blockIdx.x * 64;

    const int xrow = tid >> 2;
    const int xq   = tid & 3;

    float acc[3][4][4] = {};
    float4 pxa, pxb;
    uint4 pw[6];

    {
        const float* s = &x[(size_t)(row0 + xrow) * CC + xq * 8];
        pxa = *reinterpret_cast<const float4*>(s);
        pxb = *reinterpret_cast<const float4*>(s + 4);
#pragma unroll
        for (int u = 0; u < 6; u++) {
            int lin = u * 256 + tid;
            int t = lin >> 8, w = lin & 255;
            int n = w >> 2, kg = w & 3;
            pw[u] = *reinterpret_cast<const uint4*>(
                &g_wt[((size_t)t * HS + n) * CC + kg * 8]);
        }
    }

    for (int c = 0; c < 32; c++) {
        if (c) __syncthreads();
        {
            float v[8] = {pxa.x, pxa.y, pxa.z, pxa.w, pxb.x, pxb.y, pxb.z, pxb.w};
            float h[8], l[8];
#pragma unroll
            for (int e = 0; e < 8; e++) {
                h[e] = bfhi(v[e]);
                l[e] = v[e] - h[e];
            }
            *reinterpret_cast<uint4*>(&Xh[xrow * 40 + xq * 8]) =
                make_uint4(bfpack(h[0], h[1]), bfpack(h[2], h[3]),
                           bfpack(h[4], h[5]), bfpack(h[6], h[7]));
            *reinterpret_cast<uint4*>(&Xl[xrow * 40 + xq * 8]) =
                make_uint4(bfpack(l[0], l[1]), bfpack(l[2], l[3]),
                           bfpack(l[4], l[5]), bfpack(l[6], l[7]));
#pragma unroll
            for (int u = 0; u < 6; u++) {
                int lin = u * 256 + tid;
                int t = lin >> 8, w = lin & 255;
                int n = w >> 2, kg = w & 3;
                *reinterpret_cast<uint4*>(&Wt[t * 2560 + n * 40 + kg * 8]) = pw[u];
            }
        }
        __syncthreads();

        if (c < 31) {
            const int kc = (c + 1) * 32;
            const float* s = &x[(size_t)(row0 + xrow) * CC + kc + xq * 8];
            pxa = *reinterpret_cast<const float4*>(s);
            pxb = *reinterpret_cast<const float4*>(s + 4);
#pragma unroll
            for (int u = 0; u < 6; u++) {
                int lin = u * 256 + tid;
                int t = lin >> 8, w = lin & 255;
                int n = w >> 2, kg = w & 3;
                pw[u] = *reinterpret_cast<const uint4*>(
                    &g_wt[((size_t)t * HS + n) * CC + kc + kg * 8]);
            }
        }

        u32 Ah[2][4], Al[2][4];
#pragma unroll
        for (int ks = 0; ks < 2; ks++) {
            int k0 = ks * 16;
            int r1 = (wm * 16 + lr) * 40, r2 = r1 + 8 * 40;
            Ah[ks][0] = *reinterpret_cast<u32*>(&Xh[r1 + k0 + lc2]);
            Ah[ks][1] = *reinterpret_cast<u32*>(&Xh[r2 + k0 + lc2]);
            Ah[ks][2] = *reinterpret_cast<u32*>(&Xh[r1 + k0 + lc2 + 8]);
            Ah[ks][3] = *reinterpret_cast<u32*>(&Xh[r2 + k0 + lc2 + 8]);
            Al[ks][0] = *reinterpret_cast<u32*>(&Xl[r1 + k0 + lc2]);
            Al[ks][1] = *reinterpret_cast<u32*>(&Xl[r2 + k0 + lc2]);
            Al[ks][2] = *reinterpret_cast<u32*>(&Xl[r1 + k0 + lc2 + 8]);
            Al[ks][3] = *reinterpret_cast<u32*>(&Xl[r2 + k0 + lc2 + 8]);
        }

#pragma unroll
        for (int mat = 0; mat < 3; mat++) {
            const __nv_bfloat16* Wh = &Wt[(mat * 2) * 2560];
            const __nv_bfloat16* Wl = Wh + 2560;
#pragma unroll
            for (int nt = 0; nt < 4; nt++) {
                int nr = (wn * 32 + nt * 8 + lr) * 40;
                float* D = acc[mat][nt];
#pragma unroll
                for (int ks = 0; ks < 2; ks++) {
                    int k0 = ks * 16;
                    u32 bh0 = *reinterpret_cast<const u32*>(&Wh[nr + k0 + lc2]);
                    u32 bh1 = *reinterpret_cast<const u32*>(&Wh[nr + k0 + lc2 + 8]);
                    u32 bl0 = *reinterpret_cast<const u32*>(&Wl[nr + k0 + lc2]);
                    u32 bl1 = *reinterpret_cast<const u32*>(&Wl[nr + k0 + lc2 + 8]);
                    mma16816(D, Ah[ks], bh0, bh1);
                    mma16816(D, Al[ks], bh0, bh1);
                    mma16816(D, Ah[ks], bl0, bl1);
                }
            }
        }
    }

#pragma unroll
    for (int mat = 0; mat < 3; mat++) {
        float* dst = (mat == 0) ? g_q : (mat == 1) ? g_k : g_v;
#pragma unroll
        for (int nt = 0; nt < 4; nt++) {
            int col = wn * 32 + nt * 8 + lc2;
            size_t r = (size_t)(row0 + wm * 16 + lr);
            *reinterpret_cast<float2*>(&dst[r * HS + col]) =
                make_float2(acc[mat][nt][0], acc[mat][nt][1]);
            *reinterpret_cast<float2*>(&dst[(r + 8) * HS + col]) =
                make_float2(acc[mat][nt][2], acc[mat][nt][3]);
        }
    }
}

// ---------------------------------------------------------------------------
// Kernel 2a: Q/K -> bf16 hi/lo (Q pre-scaled by SCALE).
// ---------------------------------------------------------------------------
__global__ __launch_bounds__(256) void qkconv_kernel() {
    int idx = blockIdx.x * 256 + threadIdx.x;
    bool isK = blockIdx.y;
    float v = (isK ? g_k : g_q)[idx];
    if (!isK) v *= SCALE;
    __nv_bfloat16 h = __float2bfloat16_rn(v);
    float lo = v - __bfloat162float(h);
    if (isK) { g_kh[idx] = h; g_kl[idx] = __float2bfloat16_rn(lo); }
    else     { g_qh[idx] = h; g_ql[idx] = __float2bfloat16_rn(lo); }
}

// ---------------------------------------------------------------------------
// Kernel 2b: V -> transposed bf16 hi/lo:  g_vt*[b][d][t] = split(g_v[b][t][d])
// ---------------------------------------------------------------------------
__global__ __launch_bounds__(256) void vtrans_kernel() {
    __shared__ float sm[32][33];
    const int tx = threadIdx.x & 31;
    const int ty = threadIdx.x >> 5;      // 0..7
    const int t0 = blockIdx.x * 32;
    const int d0 = blockIdx.y * 32;
    const int b  = blockIdx.z;

#pragma unroll
    for (int i = 0; i < 4; i++)
        sm[ty + 8 * i][tx] =
            g_v[((size_t)(b * TT + t0 + ty + 8 * i)) * HS + d0 + tx];
    __syncthreads();
#pragma unroll
    for (int i = 0; i < 4; i++) {
        int d = d0 + ty + 8 * i;
        float v = sm[tx][ty + 8 * i];
        __nv_bfloat16 h = __float2bfloat16_rn(v);
        float lo = v - __bfloat162float(h);
        size_t a = ((size_t)b * HS + d) * TT + t0 + tx;
        g_vth[a] = h;
        g_vtl[a] = __float2bfloat16_rn(lo);
    }
}

// ---------------------------------------------------------------------------
// Kernel 3: flash-attention partials via mma.sync bf16x3.
// grid = (32 q-tiles, KSPLIT, 4 batches), 128 threads (4 warps).
// Smem rows are 64 halfs wide -> pitch 72 (64 + 8 pad).  FIXED from R11.
// ---------------------------------------------------------------------------
#define APITCH 72
__global__ __launch_bounds__(128) void attn_mma_kernel() {
    const int qtile = blockIdx.x;
    const int split = blockIdx.y;
    const int b     = blockIdx.z;

    const int tid  = threadIdx.x;
    const int warp = tid >> 5;
    const int lane = tid & 31;
    const int lr   = lane >> 2;          // 0..7
    const int lq2  = (lane & 3) * 2;     // 0,2,4,6
    const int q0   = qtile * 64;
    const int r_a  = warp * 16 + lr;     // local q-row (and r_a+8)

    __shared__ __align__(16) __nv_bfloat16 Ksm[2][64 * APITCH];  // hi/lo, [key][dim]
    __shared__ __align__(16) __nv_bfloat16 Vsm[2][64 * APITCH];  // hi/lo, [dim][key]

    // Q fragments (once per block, direct LDG)
    u32 qh[4][4], ql[4][4];
    {
        size_t ra = (size_t)(b * TT + q0 + r_a) * HS;
        size_t rb = ra + 8 * HS;
#pragma unroll
        for (int ks = 0; ks < 4; ks++) {
            int o = ks * 16 + lq2;
            qh[ks][0] = *reinterpret_cast<const u32*>(&g_qh[ra + o]);
            qh[ks][1] = *reinterpret_cast<const u32*>(&g_qh[rb + o]);
            qh[ks][2] = *reinterpret_cast<const u32*>(&g_qh[ra + o + 8]);
            qh[ks][3] = *reinterpret_cast<const u32*>(&g_qh[rb + o + 8]);
            ql[ks][0] = *reinterpret_cast<const u32*>(&g_ql[ra + o]);
            ql[ks][1] = *reinterpret_cast<const u32*>(&g_ql[rb + o]);
            ql[ks][2] = *reinterpret_cast<const u32*>(&g_ql[ra + o + 8]);
            ql[ks][3] = *reinterpret_cast<const u32*>(&g_ql[rb + o + 8]);
        }
    }

    float O[8][4] = {};
    float m_a = -1e30f, m_b = -1e30f, l_a = 0.f, l_b = 0.f;

    for (int kt = split; kt <= qtile; kt += KSPLIT) {
        const int k0 = kt * 64;
        __syncthreads();
        // load K (hi/lo) and Vt (hi/lo) tiles
#pragma unroll
        for (int u = 0; u < 4; u++) {
            int lin = u * 128 + tid;     // 0..511
            int row = lin >> 3;          // 0..63
            int g   = lin & 7;
            size_t kb = ((size_t)(b * TT + k0 + row)) * HS + g * 8;
            size_t vb = ((size_t)b * HS + row) * TT + k0 + g * 8;
            *reinterpret_cast<uint4*>(&Ksm[0][row * APITCH + g * 8]) =
                *reinterpret_cast<const uint4*>(&g_kh[kb]);
            *reinterpret_cast<uint4*>(&Ksm[1][row * APITCH + g * 8]) =
                *reinterpret_cast<const uint4*>(&g_kl[kb]);
            *reinterpret_cast<uint4*>(&Vsm[0][row * APITCH + g * 8]) =
                *reinterpret_cast<const uint4*>(&g_vth[vb]);
            *reinterpret_cast<uint4*>(&Vsm[1][row * APITCH + g * 8]) =
                *reinterpret_cast<const uint4*>(&g_vtl[vb]);
        }
        __syncthreads();

        // ---- S = Qs K^T  (8 n-tiles of 8 keys, 4 k-steps, 3 terms) ----
        float D[8][4] = {};
#pragma unroll
        for (int ks = 0; ks < 4; ks++) {
            int ko = ks * 16 + lq2;
#pragma unroll
            for (int nt = 0; nt < 8; nt++) {
                int nr = (nt * 8 + lr) * APITCH + ko;
                u32 bh0 = *reinterpret_cast<u32*>(&Ksm[0][nr]);
                u32 bh1 = *reinterpret_cast<u32*>(&Ksm[0][nr + 8]);
                u32 bl0 = *reinterpret_cast<u32*>(&Ksm[1][nr]);
                u32 bl1 = *reinterpret_cast<u32*>(&Ksm[1][nr + 8]);
                mma16816(D[nt], qh[ks], bh0, bh1);
                mma16816(D[nt], ql[ks], bh0, bh1);
                mma16816(D[nt], qh[ks], bl0, bl1);
            }
        }

        // causal mask on the diagonal tile
        if (kt == qtile) {
#pragma unroll
            for (int nt = 0; nt < 8; nt++) {
#pragma unroll
                for (int j = 0; j < 2; j++) {
                    int col = nt * 8 + lq2 + j;
                    if (col > r_a)     D[nt][j]     = -1e30f;
                    if (col > r_a + 8) D[nt][2 + j] = -1e30f;
                }
            }
        }

        // ---- online softmax (rows on 4 lanes: shfl over lanes 1,2) ----
        float tm_a = -1e30f, tm_b = -1e30f;
#pragma unroll
        for (int nt = 0; nt < 8; nt++) {
            tm_a = fmaxf(tm_a, fmaxf(D[nt][0], D[nt][1]));
            tm_b = fmaxf(tm_b, fmaxf(D[nt][2], D[nt][3]));
        }
#pragma unroll
        for (int o = 1; o < 4; o <<= 1) {
            tm_a = fmaxf(tm_a, __shfl_xor_sync(0xffffffffu, tm_a, o));
            tm_b = fmaxf(tm_b, __shfl_xor_sync(0xffffffffu, tm_b, o));
        }
        float nm_a = fmaxf(m_a, tm_a), nm_b = fmaxf(m_b, tm_b);
        float cor_a = __expf(m_a - nm_a), cor_b = __expf(m_b - nm_b);
        float rs_a = 0.f, rs_b = 0.f;
#pragma unroll
        for (int nt = 0; nt < 8; nt++) {
            D[nt][0] = __expf(D[nt][0] - nm_a);
            D[nt][1] = __expf(D[nt][1] - nm_a);
            D[nt][2] = __expf(D[nt][2] - nm_b);
            D[nt][3] = __expf(D[nt][3] - nm_b);
            rs_a += D[nt][0] + D[nt][1];
            rs_b += D[nt][2] + D[nt][3];
        }
#pragma unroll
        for (int o = 1; o < 4; o <<= 1) {
            rs_a += __shfl_xor_sync(0xffffffffu, rs_a, o);
            rs_b += __shfl_xor_sync(0xffffffffu, rs_b, o);
        }
        l_a = l_a * cor_a + rs_a;  m_a = nm_a;
        l_b = l_b * cor_b + rs_b;  m_b = nm_b;
#pragma unroll
        for (int nt = 0; nt < 8; nt++) {
            O[nt][0] *= cor_a; O[nt][1] *= cor_a;
            O[nt][2] *= cor_b; O[nt][3] *= cor_b;
        }

        // ---- O += P V   (P packed from D in registers, hi/lo) ----
#pragma unroll
        for (int ks = 0; ks < 4; ks++) {
            float h00 = bfhi(D[2*ks][0]),   l00 = D[2*ks][0]   - h00;
            float h01 = bfhi(D[2*ks][1]),   l01 = D[2*ks][1]   - h01;
            float h02 = bfhi(D[2*ks][2]),   l02 = D[2*ks][2]   - h02;
            float h03 = bfhi(D[2*ks][3]),   l03 = D[2*ks][3]   - h03;
            float h10 = bfhi(D[2*ks+1][0]), l10 = D[2*ks+1][0] - h10;
            float h11 = bfhi(D[2*ks+1][1]), l11 = D[2*ks+1][1] - h11;
            float h12 = bfhi(D[2*ks+1][2]), l12 = D[2*ks+1][2] - h12;
            float h13 = bfhi(D[2*ks+1][3]), l13 = D[2*ks+1][3] - h13;
            u32 PH[4] = {bfpack(h00, h01), bfpack(h02, h03),
                         bfpack(h10, h11), bfpack(h12, h13)};
            u32 PL[4] = {bfpack(l00, l01), bfpack(l02, l03),
                         bfpack(l10, l11), bfpack(l12, l13)};
            int ko = ks * 16 + lq2;
#pragma unroll
            for (int nt = 0; nt < 8; nt++) {
                int nr = (nt * 8 + lr) * APITCH + ko;
                u32 bh0 = *reinterpret_cast<u32*>(&Vsm[0][nr]);
                u32 bh1 = *reinterpret_cast<u32*>(&Vsm[0][nr + 8]);
                u32 bl0 = *reinterpret_cast<u32*>(&Vsm[1][nr]);
                u32 bl1 = *reinterpret_cast<u32*>(&Vsm[1][nr + 8]);
                mma16816(O[nt], PH, bh0, bh1);
                mma16816(O[nt], PL, bh0, bh1);
                mma16816(O[nt], PH, bl0, bl1);
            }
        }
    }

    // ---- write split partials ----
    const size_t base = (size_t)(b * KSPLIT + split) * TT + q0;
#pragma unroll
    for (int nt = 0; nt < 8; nt++) {
        int col = nt * 8 + lq2;
        *reinterpret_cast<float2*>(&g_pacc[(base + r_a) * HS + col]) =
            make_float2(O[nt][0], O[nt][1]);
        *reinterpret_cast<float2*>(&g_pacc[(base + r_a + 8) * HS + col]) =
            make_float2(O[nt][2], O[nt][3]);
    }
    if ((lane & 3) == 0) {
        g_pm[base + r_a] = m_a;     g_pl[base + r_a] = l_a;
        g_pm[base + r_a + 8] = m_b; g_pl[base + r_a + 8] = l_b;
    }
}

// ---------------------------------------------------------------------------
// Kernel 4: combine split partials into the final output.
// ---------------------------------------------------------------------------
__global__ __launch_bounds__(256) void combine_kernel(float* __restrict__ out) {
    const int idx = blockIdx.x * 256 + threadIdx.x;
    const int d   = idx & (HS - 1);
    const int row = idx >> 6;
    const int b   = row >> 11;
    const int q   = row & (TT - 1);

    float M = -1e30f;
#pragma unroll
    for (int s = 0; s < KSPLIT; s++)
        M = fmaxf(M, g_pm[(size_t)(b * KSPLIT + s) * TT + q]);

    float L = 0.f, A = 0.f;
#pragma unroll
    for (int s = 0; s < KSPLIT; s++) {
        size_t pb = (size_t)(b * KSPLIT + s) * TT + q;
        float w = __expf(g_pm[pb] - M);
        L += g_pl[pb] * w;
        A += g_pacc[pb * HS + d] * w;
    }
    out[idx] = A / L;
}

// ---------------------------------------------------------------------------
extern "C" void kernel_launch(void* const* d_in, const int* in_sizes, int n_in,
                              void* d_out, int out_size) {
    const float* x  = (const float*)d_in[0];
    const float* Wq = (const float*)d_in[1];
    const float* Wk = (const float*)d_in[2];
    const float* Wv = (const float*)d_in[3];
    float* out = (float*)d_out;

    wconvert_kernel<<<(3 * HS * CC) / 256, 256>>>(Wq, Wk, Wv);
    qkv_mma_kernel<<<(BB * TT) / 64, 256>>>(x);
    qkconv_kernel<<<dim3((BB * TT * HS) / 256, 2), 256>>>();
    vtrans_kernel<<<dim3(TT / 32, HS / 32, BB), 256>>>();
    attn_mma_kernel<<<dim3(TT / 64, KSPLIT, BB), 128>>>();
    combine_kernel<<<(BB * TT * HS) / 256, 256>>>(out);
}

// round 14
// speedup vs baseline: 2.1076x; 1.0288x over previous
#include <cuda_runtime.h>
#include <cuda_bf16.h>

#define BB 4
#define TT 2048
#define CC 1024
#define HS 64
#define KSPLIT 8
#define SCALE 0.03125f   // C^-0.5 = 1024^-0.5

typedef unsigned long long u64;
typedef unsigned int u32;

// ---- warp-level HMMA: D[16x8] += A[16x16] * B[16x8]  (bf16 in, f32 acc) ----
__device__ __forceinline__ void mma16816(float* d, const u32* a, u32 b0, u32 b1) {
    asm volatile(
        "mma.sync.aligned.m16n8k16.row.col.f32.bf16.bf16.f32 "
        "{%0,%1,%2,%3},{%4,%5,%6,%7},{%8,%9},{%0,%1,%2,%3};"
        : "+f"(d[0]), "+f"(d[1]), "+f"(d[2]), "+f"(d[3])
        : "r"(a[0]), "r"(a[1]), "r"(a[2]), "r"(a[3]), "r"(b0), "r"(b1));
}

__device__ __forceinline__ u32 bfpack(float a, float b) {
    __nv_bfloat162 t = __floats2bfloat162_rn(a, b);
    return *reinterpret_cast<u32*>(&t);
}
__device__ __forceinline__ float bfhi(float v) {
    return __bfloat162float(__float2bfloat16_rn(v));
}

// Scratch (static device allocations; no cudaMalloc allowed)
__device__ float g_q[BB * TT * HS];
__device__ float g_k[BB * TT * HS];
__device__ float g_v[BB * TT * HS];
__device__ float g_p2[3 * BB * TT * HS];    // qkv K-split half-1 partials
__device__ float g_pacc[(size_t)BB * KSPLIT * TT * HS];
__device__ float g_pm[BB * KSPLIT * TT];
__device__ float g_pl[BB * KSPLIT * TT];
// W transposed + bf16 hi/lo split: [mat][part][n][k]
__device__ __align__(16) __nv_bfloat16 g_wt[3 * 2 * HS * CC];
// attention operands, bf16 hi/lo
__device__ __align__(16) __nv_bfloat16 g_qh[BB * TT * HS];  // pre-scaled
__device__ __align__(16) __nv_bfloat16 g_ql[BB * TT * HS];
__device__ __align__(16) __nv_bfloat16 g_kh[BB * TT * HS];
__device__ __align__(16) __nv_bfloat16 g_kl[BB * TT * HS];
__device__ __align__(16) __nv_bfloat16 g_vth[BB * HS * TT]; // transposed [b][d][t]
__device__ __align__(16) __nv_bfloat16 g_vtl[BB * HS * TT];

// ---------------------------------------------------------------------------
// Kernel 0: transpose + split W into bf16 hi/lo.
// ---------------------------------------------------------------------------
__global__ __launch_bounds__(256) void wconvert_kernel(
    const float* __restrict__ Wq,
    const float* __restrict__ Wk,
    const float* __restrict__ Wv) {
    int idx = blockIdx.x * 256 + threadIdx.x;
    int k = idx & (CC - 1);
    int n = (idx >> 10) & (HS - 1);
    int m = idx >> 16;
    const float* W = (m == 0) ? Wq : (m == 1) ? Wk : Wv;
    float v = W[(size_t)k * HS + n];
    __nv_bfloat16 hi = __float2bfloat16_rn(v);
    float lo = v - __bfloat162float(hi);
    size_t base = ((size_t)(m * 2) * HS + n) * CC + k;
    g_wt[base]           = hi;
    g_wt[base + HS * CC] = __float2bfloat16_rn(lo);
}

// ---------------------------------------------------------------------------
// Kernel 1: QKV via mma.sync bf16x3, K-split over blockIdx.y (2 halves of 512).
// grid = (128, 2), 256 threads.  Half 0 -> g_q/g_k/g_v, half 1 -> g_p2.
// ---------------------------------------------------------------------------
__global__ __launch_bounds__(256) void qkv_mma_kernel(const float* __restrict__ x) {
    __shared__ __align__(16) __nv_bfloat16 Xh[64 * 40];
    __shared__ __align__(16) __nv_bfloat16 Xl[64 * 40];
    __shared__ __align__(16) __nv_bfloat16 Wt[6 * 64 * 40];

    const int tid  = threadIdx.x;
    const int warp = tid >> 5;
    const int lane = tid & 31;
    const int wm = warp & 3;
    const int wn = warp >> 2;
    const int lr  = lane >> 2;
    const int lc2 = (lane & 3) * 2;
    const int row0 = blockIdx.x * 64;
    const int kbase = blockIdx.y * (CC / 2);

    const int xrow = tid >> 2;
    const int xq   = tid & 3;

    float acc[3][4][4] = {};
    float4 pxa, pxb;
    uint4 pw[6];

    {
        const float* s = &x[(size_t)(row0 + xrow) * CC + kbase + xq * 8];
        pxa = *reinterpret_cast<const float4*>(s);
        pxb = *reinterpret_cast<const float4*>(s + 4);
#pragma unroll
        for (int u = 0; u < 6; u++) {
            int lin = u * 256 + tid;
            int t = lin >> 8, w = lin & 255;
            int n = w >> 2, kg = w & 3;
            pw[u] = *reinterpret_cast<const uint4*>(
                &g_wt[((size_t)t * HS + n) * CC + kbase + kg * 8]);
        }
    }

    for (int c = 0; c < 16; c++) {
        if (c) __syncthreads();
        {
            float v[8] = {pxa.x, pxa.y, pxa.z, pxa.w, pxb.x, pxb.y, pxb.z, pxb.w};
            float h[8], l[8];
#pragma unroll
            for (int e = 0; e < 8; e++) {
                h[e] = bfhi(v[e]);
                l[e] = v[e] - h[e];
            }
            *reinterpret_cast<uint4*>(&Xh[xrow * 40 + xq * 8]) =
                make_uint4(bfpack(h[0], h[1]), bfpack(h[2], h[3]),
                           bfpack(h[4], h[5]), bfpack(h[6], h[7]));
            *reinterpret_cast<uint4*>(&Xl[xrow * 40 + xq * 8]) =
                make_uint4(bfpack(l[0], l[1]), bfpack(l[2], l[3]),
                           bfpack(l[4], l[5]), bfpack(l[6], l[7]));
#pragma unroll
            for (int u = 0; u < 6; u++) {
                int lin = u * 256 + tid;
                int t = lin >> 8, w = lin & 255;
                int n = w >> 2, kg = w & 3;
                *reinterpret_cast<uint4*>(&Wt[t * 2560 + n * 40 + kg * 8]) = pw[u];
            }
        }
        __syncthreads();

        if (c < 15) {
            const int kc = kbase + (c + 1) * 32;
            const float* s = &x[(size_t)(row0 + xrow) * CC + kc + xq * 8];
            pxa = *reinterpret_cast<const float4*>(s);
            pxb = *reinterpret_cast<const float4*>(s + 4);
#pragma unroll
            for (int u = 0; u < 6; u++) {
                int lin = u * 256 + tid;
                int t = lin >> 8, w = lin & 255;
                int n = w >> 2, kg = w & 3;
                pw[u] = *reinterpret_cast<const uint4*>(
                    &g_wt[((size_t)t * HS + n) * CC + kc + kg * 8]);
            }
        }

        u32 Ah[2][4], Al[2][4];
#pragma unroll
        for (int ks = 0; ks < 2; ks++) {
            int k0 = ks * 16;
            int r1 = (wm * 16 + lr) * 40, r2 = r1 + 8 * 40;
            Ah[ks][0] = *reinterpret_cast<u32*>(&Xh[r1 + k0 + lc2]);
            Ah[ks][1] = *reinterpret_cast<u32*>(&Xh[r2 + k0 + lc2]);
            Ah[ks][2] = *reinterpret_cast<u32*>(&Xh[r1 + k0 + lc2 + 8]);
            Ah[ks][3] = *reinterpret_cast<u32*>(&Xh[r2 + k0 + lc2 + 8]);
            Al[ks][0] = *reinterpret_cast<u32*>(&Xl[r1 + k0 + lc2]);
            Al[ks][1] = *reinterpret_cast<u32*>(&Xl[r2 + k0 + lc2]);
            Al[ks][2] = *reinterpret_cast<u32*>(&Xl[r1 + k0 + lc2 + 8]);
            Al[ks][3] = *reinterpret_cast<u32*>(&Xl[r2 + k0 + lc2 + 8]);
        }

#pragma unroll
        for (int mat = 0; mat < 3; mat++) {
            const __nv_bfloat16* Wh = &Wt[(mat * 2) * 2560];
            const __nv_bfloat16* Wl = Wh + 2560;
#pragma unroll
            for (int nt = 0; nt < 4; nt++) {
                int nr = (wn * 32 + nt * 8 + lr) * 40;
                float* D = acc[mat][nt];
#pragma unroll
                for (int ks = 0; ks < 2; ks++) {
                    int k0 = ks * 16;
                    u32 bh0 = *reinterpret_cast<const u32*>(&Wh[nr + k0 + lc2]);
                    u32 bh1 = *reinterpret_cast<const u32*>(&Wh[nr + k0 + lc2 + 8]);
                    u32 bl0 = *reinterpret_cast<const u32*>(&Wl[nr + k0 + lc2]);
                    u32 bl1 = *reinterpret_cast<const u32*>(&Wl[nr + k0 + lc2 + 8]);
                    mma16816(D, Ah[ks], bh0, bh1);
                    mma16816(D, Al[ks], bh0, bh1);
                    mma16816(D, Ah[ks], bl0, bl1);
                }
            }
        }
    }

#pragma unroll
    for (int mat = 0; mat < 3; mat++) {
        float* dst = (blockIdx.y == 0)
            ? ((mat == 0) ? g_q : (mat == 1) ? g_k : g_v)
            : &g_p2[(size_t)mat * BB * TT * HS];
#pragma unroll
        for (int nt = 0; nt < 4; nt++) {
            int col = wn * 32 + nt * 8 + lc2;
            size_t r = (size_t)(row0 + wm * 16 + lr);
            *reinterpret_cast<float2*>(&dst[r * HS + col]) =
                make_float2(acc[mat][nt][0], acc[mat][nt][1]);
            *reinterpret_cast<float2*>(&dst[(r + 8) * HS + col]) =
                make_float2(acc[mat][nt][2], acc[mat][nt][3]);
        }
    }
}

// ---------------------------------------------------------------------------
// Kernel 2: merge K-halves AND convert.
// Q: sum, *SCALE, split -> g_qh/g_ql.   K: sum, split -> g_kh/g_kl.
// V: sum -> g_v fp32 (vtrans consumes it).
// Each thread handles 8 consecutive floats.  grid = 768, 256 threads.
// ---------------------------------------------------------------------------
__global__ __launch_bounds__(256) void merge_kernel() {
    const int t = blockIdx.x * 256 + threadIdx.x;
    const int per = (BB * TT * HS) / 8;          // 65536 threads per matrix
    const int m = t / per;
    const int i = (t - m * per) * 8;
    const float* a = (m == 0) ? g_q : (m == 1) ? g_k : g_v;
    const float* p = &g_p2[(size_t)m * BB * TT * HS];

    float4 a0 = *reinterpret_cast<const float4*>(&a[i]);
    float4 a1 = *reinterpret_cast<const float4*>(&a[i + 4]);
    float4 b0 = *reinterpret_cast<const float4*>(&p[i]);
    float4 b1 = *reinterpret_cast<const float4*>(&p[i + 4]);
    float v[8] = {a0.x + b0.x, a0.y + b0.y, a0.z + b0.z, a0.w + b0.w,
                  a1.x + b1.x, a1.y + b1.y, a1.z + b1.z, a1.w + b1.w};

    if (m == 2) {
        *reinterpret_cast<float4*>(&g_v[i])     = make_float4(v[0], v[1], v[2], v[3]);
        *reinterpret_cast<float4*>(&g_v[i + 4]) = make_float4(v[4], v[5], v[6], v[7]);
        return;
    }
    if (m == 0) {
#pragma unroll
        for (int e = 0; e < 8; e++) v[e] *= SCALE;
    }
    float h[8], l[8];
#pragma unroll
    for (int e = 0; e < 8; e++) {
        h[e] = bfhi(v[e]);
        l[e] = v[e] - h[e];
    }
    __nv_bfloat16* dh = (m == 0) ? g_qh : g_kh;
    __nv_bfloat16* dl = (m == 0) ? g_ql : g_kl;
    *reinterpret_cast<uint4*>(&dh[i]) =
        make_uint4(bfpack(h[0], h[1]), bfpack(h[2], h[3]),
                   bfpack(h[4], h[5]), bfpack(h[6], h[7]));
    *reinterpret_cast<uint4*>(&dl[i]) =
        make_uint4(bfpack(l[0], l[1]), bfpack(l[2], l[3]),
                   bfpack(l[4], l[5]), bfpack(l[6], l[7]));
}

// ---------------------------------------------------------------------------
// Kernel 3: V -> transposed bf16 hi/lo:  g_vt*[b][d][t] = split(g_v[b][t][d])
// ---------------------------------------------------------------------------
__global__ __launch_bounds__(256) void vtrans_kernel() {
    __shared__ float sm[32][33];
    const int tx = threadIdx.x & 31;
    const int ty = threadIdx.x >> 5;      // 0..7
    const int t0 = blockIdx.x * 32;
    const int d0 = blockIdx.y * 32;
    const int b  = blockIdx.z;

#pragma unroll
    for (int i = 0; i < 4; i++)
        sm[ty + 8 * i][tx] =
            g_v[((size_t)(b * TT + t0 + ty + 8 * i)) * HS + d0 + tx];
    __syncthreads();
#pragma unroll
    for (int i = 0; i < 4; i++) {
        int d = d0 + ty + 8 * i;
        float v = sm[tx][ty + 8 * i];
        __nv_bfloat16 h = __float2bfloat16_rn(v);
        float lo = v - __bfloat162float(h);
        size_t a = ((size_t)b * HS + d) * TT + t0 + tx;
        g_vth[a] = h;
        g_vtl[a] = __float2bfloat16_rn(lo);
    }
}

// ---------------------------------------------------------------------------
// Kernel 4: flash-attention partials via mma.sync bf16x3 (R13 WIN, unchanged).
// ---------------------------------------------------------------------------
#define APITCH 72
__global__ __launch_bounds__(128) void attn_mma_kernel() {
    const int qtile = blockIdx.x;
    const int split = blockIdx.y;
    const int b     = blockIdx.z;

    const int tid  = threadIdx.x;
    const int warp = tid >> 5;
    const int lane = tid & 31;
    const int lr   = lane >> 2;
    const int lq2  = (lane & 3) * 2;
    const int q0   = qtile * 64;
    const int r_a  = warp * 16 + lr;

    __shared__ __align__(16) __nv_bfloat16 Ksm[2][64 * APITCH];
    __shared__ __align__(16) __nv_bfloat16 Vsm[2][64 * APITCH];

    u32 qh[4][4], ql[4][4];
    {
        size_t ra = (size_t)(b * TT + q0 + r_a) * HS;
        size_t rb = ra + 8 * HS;
#pragma unroll
        for (int ks = 0; ks < 4; ks++) {
            int o = ks * 16 + lq2;
            qh[ks][0] = *reinterpret_cast<const u32*>(&g_qh[ra + o]);
            qh[ks][1] = *reinterpret_cast<const u32*>(&g_qh[rb + o]);
            qh[ks][2] = *reinterpret_cast<const u32*>(&g_qh[ra + o + 8]);
            qh[ks][3] = *reinterpret_cast<const u32*>(&g_qh[rb + o + 8]);
            ql[ks][0] = *reinterpret_cast<const u32*>(&g_ql[ra + o]);
            ql[ks][1] = *reinterpret_cast<const u32*>(&g_ql[rb + o]);
            ql[ks][2] = *reinterpret_cast<const u32*>(&g_ql[ra + o + 8]);
            ql[ks][3] = *reinterpret_cast<const u32*>(&g_ql[rb + o + 8]);
        }
    }

    float O[8][4] = {};
    float m_a = -1e30f, m_b = -1e30f, l_a = 0.f, l_b = 0.f;

    for (int kt = split; kt <= qtile; kt += KSPLIT) {
        const int k0 = kt * 64;
        __syncthreads();
#pragma unroll
        for (int u = 0; u < 4; u++) {
            int lin = u * 128 + tid;
            int row = lin >> 3;
            int g   = lin & 7;
            size_t kb = ((size_t)(b * TT + k0 + row)) * HS + g * 8;
            size_t vb = ((size_t)b * HS + row) * TT + k0 + g * 8;
            *reinterpret_cast<uint4*>(&Ksm[0][row * APITCH + g * 8]) =
                *reinterpret_cast<const uint4*>(&g_kh[kb]);
            *reinterpret_cast<uint4*>(&Ksm[1][row * APITCH + g * 8]) =
                *reinterpret_cast<const uint4*>(&g_kl[kb]);
            *reinterpret_cast<uint4*>(&Vsm[0][row * APITCH + g * 8]) =
                *reinterpret_cast<const uint4*>(&g_vth[vb]);
            *reinterpret_cast<uint4*>(&Vsm[1][row * APITCH + g * 8]) =
                *reinterpret_cast<const uint4*>(&g_vtl[vb]);
        }
        __syncthreads();

        float D[8][4] = {};
#pragma unroll
        for (int ks = 0; ks < 4; ks++) {
            int ko = ks * 16 + lq2;
#pragma unroll
            for (int nt = 0; nt < 8; nt++) {
                int nr = (nt * 8 + lr) * APITCH + ko;
                u32 bh0 = *reinterpret_cast<u32*>(&Ksm[0][nr]);
                u32 bh1 = *reinterpret_cast<u32*>(&Ksm[0][nr + 8]);
                u32 bl0 = *reinterpret_cast<u32*>(&Ksm[1][nr]);
                u32 bl1 = *reinterpret_cast<u32*>(&Ksm[1][nr + 8]);
                mma16816(D[nt], qh[ks], bh0, bh1);
                mma16816(D[nt], ql[ks], bh0, bh1);
                mma16816(D[nt], qh[ks], bl0, bl1);
            }
        }

        if (kt == qtile) {
#pragma unroll
            for (int nt = 0; nt < 8; nt++) {
#pragma unroll
                for (int j = 0; j < 2; j++) {
                    int col = nt * 8 + lq2 + j;
                    if (col > r_a)     D[nt][j]     = -1e30f;
                    if (col > r_a + 8) D[nt][2 + j] = -1e30f;
                }
            }
        }

        float tm_a = -1e30f, tm_b = -1e30f;
#pragma unroll
        for (int nt = 0; nt < 8; nt++) {
            tm_a = fmaxf(tm_a, fmaxf(D[nt][0], D[nt][1]));
            tm_b = fmaxf(tm_b, fmaxf(D[nt][2], D[nt][3]));
        }
#pragma unroll
        for (int o = 1; o < 4; o <<= 1) {
            tm_a = fmaxf(tm_a, __shfl_xor_sync(0xffffffffu, tm_a, o));
            tm_b = fmaxf(tm_b, __shfl_xor_sync(0xffffffffu, tm_b, o));
        }
        float nm_a = fmaxf(m_a, tm_a), nm_b = fmaxf(m_b, tm_b);
        float cor_a = __expf(m_a - nm_a), cor_b = __expf(m_b - nm_b);
        float rs_a = 0.f, rs_b = 0.f;
#pragma unroll
        for (int nt = 0; nt < 8; nt++) {
            D[nt][0] = __expf(D[nt][0] - nm_a);
            D[nt][1] = __expf(D[nt][1] - nm_a);
            D[nt][2] = __expf(D[nt][2] - nm_b);
            D[nt][3] = __expf(D[nt][3] - nm_b);
            rs_a += D[nt][0] + D[nt][1];
            rs_b += D[nt][2] + D[nt][3];
        }
#pragma unroll
        for (int o = 1; o < 4; o <<= 1) {
            rs_a += __shfl_xor_sync(0xffffffffu, rs_a, o);
            rs_b += __shfl_xor_sync(0xffffffffu, rs_b, o);
        }
        l_a = l_a * cor_a + rs_a;  m_a = nm_a;
        l_b = l_b * cor_b + rs_b;  m_b = nm_b;
#pragma unroll
        for (int nt = 0; nt < 8; nt++) {
            O[nt][0] *= cor_a; O[nt][1] *= cor_a;
            O[nt][2] *= cor_b; O[nt][3] *= cor_b;
        }

#pragma unroll
        for (int ks = 0; ks < 4; ks++) {
            float h00 = bfhi(D[2*ks][0]),   l00 = D[2*ks][0]   - h00;
            float h01 = bfhi(D[2*ks][1]),   l01 = D[2*ks][1]   - h01;
            float h02 = bfhi(D[2*ks][2]),   l02 = D[2*ks][2]   - h02;
            float h03 = bfhi(D[2*ks][3]),   l03 = D[2*ks][3]   - h03;
            float h10 = bfhi(D[2*ks+1][0]), l10 = D[2*ks+1][0] - h10;
            float h11 = bfhi(D[2*ks+1][1]), l11 = D[2*ks+1][1] - h11;
            float h12 = bfhi(D[2*ks+1][2]), l12 = D[2*ks+1][2] - h12;
            float h13 = bfhi(D[2*ks+1][3]), l13 = D[2*ks+1][3] - h13;
            u32 PH[4] = {bfpack(h00, h01), bfpack(h02, h03),
                         bfpack(h10, h11), bfpack(h12, h13)};
            u32 PL[4] = {bfpack(l00, l01), bfpack(l02, l03),
                         bfpack(l10, l11), bfpack(l12, l13)};
            int ko = ks * 16 + lq2;
#pragma unroll
            for (int nt = 0; nt < 8; nt++) {
                int nr = (nt * 8 + lr) * APITCH + ko;
                u32 bh0 = *reinterpret_cast<u32*>(&Vsm[0][nr]);
                u32 bh1 = *reinterpret_cast<u32*>(&Vsm[0][nr + 8]);
                u32 bl0 = *reinterpret_cast<u32*>(&Vsm[1][nr]);
                u32 bl1 = *reinterpret_cast<u32*>(&Vsm[1][nr + 8]);
                mma16816(O[nt], PH, bh0, bh1);
                mma16816(O[nt], PL, bh0, bh1);
                mma16816(O[nt], PH, bl0, bl1);
            }
        }
    }

    const size_t base = (size_t)(b * KSPLIT + split) * TT + q0;
#pragma unroll
    for (int nt = 0; nt < 8; nt++) {
        int col = nt * 8 + lq2;
        *reinterpret_cast<float2*>(&g_pacc[(base + r_a) * HS + col]) =
            make_float2(O[nt][0], O[nt][1]);
        *reinterpret_cast<float2*>(&g_pacc[(base + r_a + 8) * HS + col]) =
            make_float2(O[nt][2], O[nt][3]);
    }
    if ((lane & 3) == 0) {
        g_pm[base + r_a] = m_a;     g_pl[base + r_a] = l_a;
        g_pm[base + r_a + 8] = m_b; g_pl[base + r_a + 8] = l_b;
    }
}

// ---------------------------------------------------------------------------
// Kernel 5: combine split partials into the final output.
// ---------------------------------------------------------------------------
__global__ __launch_bounds__(256) void combine_kernel(float* __restrict__ out) {
    const int idx = blockIdx.x * 256 + threadIdx.x;
    const int d   = idx & (HS - 1);
    const int row = idx >> 6;
    const int b   = row >> 11;
    const int q   = row & (TT - 1);

    float M = -1e30f;
#pragma unroll
    for (int s = 0; s < KSPLIT; s++)
        M = fmaxf(M, g_pm[(size_t)(b * KSPLIT + s) * TT + q]);

    float L = 0.f, A = 0.f;
#pragma unroll
    for (int s = 0; s < KSPLIT; s++) {
        size_t pb = (size_t)(b * KSPLIT + s) * TT + q;
        float w = __expf(g_pm[pb] - M);
        L += g_pl[pb] * w;
        A += g_pacc[pb * HS + d] * w;
    }
    out[idx] = A / L;
}

// ---------------------------------------------------------------------------
extern "C" void kernel_launch(void* const* d_in, const int* in_sizes, int n_in,
                              void* d_out, int out_size) {
    const float* x  = (const float*)d_in[0];
    const float* Wq = (const float*)d_in[1];
    const float* Wk = (const float*)d_in[2];
    const float* Wv = (const float*)d_in[3];
    float* out = (float*)d_out;

    wconvert_kernel<<<(3 * HS * CC) / 256, 256>>>(Wq, Wk, Wv);
    qkv_mma_kernel<<<dim3((BB * TT) / 64, 2), 256>>>(x);
    merge_kernel<<<(3 * BB * TT * HS / 8) / 256, 256>>>();
    vtrans_kernel<<<dim3(TT / 32, HS / 32, BB), 256>>>();
    attn_mma_kernel<<<dim3(TT / 64, KSPLIT, BB), 128>>>();
    combine_kernel<<<(BB * TT * HS) / 256, 256>>>(out);
}

// round 15
// speedup vs baseline: 2.2759x; 1.0799x over previous
#include <cuda_runtime.h>
#include <cuda_bf16.h>

#define BB 4
#define TT 2048
#define CC 1024
#define HS 64
#define KSPLIT 8
#define SCALE 0.03125f   // C^-0.5 = 1024^-0.5

typedef unsigned long long u64;
typedef unsigned int u32;

// ---- warp-level HMMA: D[16x8] += A[16x16] * B[16x8]  (bf16 in, f32 acc) ----
__device__ __forceinline__ void mma16816(float* d, const u32* a, u32 b0, u32 b1) {
    asm volatile(
        "mma.sync.aligned.m16n8k16.row.col.f32.bf16.bf16.f32 "
        "{%0,%1,%2,%3},{%4,%5,%6,%7},{%8,%9},{%0,%1,%2,%3};"
        : "+f"(d[0]), "+f"(d[1]), "+f"(d[2]), "+f"(d[3])
        : "r"(a[0]), "r"(a[1]), "r"(a[2]), "r"(a[3]), "r"(b0), "r"(b1));
}

__device__ __forceinline__ u32 bfpack(float a, float b) {
    __nv_bfloat162 t = __floats2bfloat162_rn(a, b);
    return *reinterpret_cast<u32*>(&t);
}
__device__ __forceinline__ float bfhi(float v) {
    return __bfloat162float(__float2bfloat16_rn(v));
}

// Scratch (static device allocations; no cudaMalloc allowed)
__device__ float g_q[BB * TT * HS];
__device__ float g_k[BB * TT * HS];
__device__ float g_v[BB * TT * HS];
__device__ float g_p2[3 * BB * TT * HS];    // qkv K-split half-1 partials
__device__ float g_pacc[(size_t)BB * KSPLIT * TT * HS];
__device__ float g_pm[BB * KSPLIT * TT];
__device__ float g_pl[BB * KSPLIT * TT];
// W in fragment-major layout: [mp=mat*2+part][chunk 0..31][nt 0..7][lane 0..31]
// each uint4 = 4 B-regs: {b0(ks0), b1(ks0), b0(ks1), b1(ks1)}
__device__ __align__(16) uint4 g_wf[6 * 32 * 8 * 32];
// attention operands, bf16 hi/lo
__device__ __align__(16) __nv_bfloat16 g_qh[BB * TT * HS];  // pre-scaled
__device__ __align__(16) __nv_bfloat16 g_ql[BB * TT * HS];
__device__ __align__(16) __nv_bfloat16 g_kh[BB * TT * HS];
__device__ __align__(16) __nv_bfloat16 g_kl[BB * TT * HS];
__device__ __align__(16) __nv_bfloat16 g_vth[BB * HS * TT]; // transposed [b][d][t]
__device__ __align__(16) __nv_bfloat16 g_vtl[BB * HS * TT];

// ---------------------------------------------------------------------------
// Kernel 0: W -> fragment-major bf16 hi/lo.
// thread = (mat, chunk, nt, lane); writes hi and lo uint4.
// ---------------------------------------------------------------------------
__global__ __launch_bounds__(256) void wconvert_kernel(
    const float* __restrict__ Wq,
    const float* __restrict__ Wk,
    const float* __restrict__ Wv) {
    int idx = blockIdx.x * 256 + threadIdx.x;   // 0 .. 3*32*8*32-1 = 24575
    int mat  = idx >> 13;
    int rem  = idx & 8191;
    int c    = rem >> 8;
    int r2   = rem & 255;
    int nt   = r2 >> 5;
    int lane = r2 & 31;
    int lr   = lane >> 2;
    int lq2  = (lane & 3) * 2;
    int n    = nt * 8 + lr;
    int kc   = c * 32;
    const float* W = (mat == 0) ? Wq : (mat == 1) ? Wk : Wv;

    float h[8], l[8];
#pragma unroll
    for (int p = 0; p < 4; p++) {               // kA,kB,kC,kD groups
        int k = kc + p * 8 + lq2;
        float v0 = W[(size_t)k * HS + n];
        float v1 = W[(size_t)(k + 1) * HS + n];
        h[p * 2]     = bfhi(v0);  l[p * 2]     = v0 - h[p * 2];
        h[p * 2 + 1] = bfhi(v1);  l[p * 2 + 1] = v1 - h[p * 2 + 1];
    }
    uint4 hv = make_uint4(bfpack(h[0], h[1]), bfpack(h[2], h[3]),
                          bfpack(h[4], h[5]), bfpack(h[6], h[7]));
    uint4 lv = make_uint4(bfpack(l[0], l[1]), bfpack(l[2], l[3]),
                          bfpack(l[4], l[5]), bfpack(l[6], l[7]));
    g_wf[(((mat * 2 + 0) * 32 + c) * 8 + nt) * 32 + lane] = hv;
    g_wf[(((mat * 2 + 1) * 32 + c) * 8 + nt) * 32 + lane] = lv;
}

// ---------------------------------------------------------------------------
// Kernel 1: QKV via mma.sync bf16x3, K-split over blockIdx.y.
// W fragments loaded via single LDS.128 per (mat, nt, part).
// grid = (128, 2), 256 threads.
// ---------------------------------------------------------------------------
__global__ __launch_bounds__(256) void qkv_mma_kernel(const float* __restrict__ x) {
    __shared__ __align__(16) __nv_bfloat16 Xh[64 * 40];
    __shared__ __align__(16) __nv_bfloat16 Xl[64 * 40];
    __shared__ __align__(16) uint4 Wf[6 * 256];   // [mp][nt*32+lane]

    const int tid  = threadIdx.x;
    const int warp = tid >> 5;
    const int lane = tid & 31;
    const int wm = warp & 3;
    const int wn = warp >> 2;
    const int lr  = lane >> 2;
    const int lc2 = (lane & 3) * 2;
    const int row0 = blockIdx.x * 64;
    const int kbase = blockIdx.y * (CC / 2);
    const int gc0   = blockIdx.y * 16;

    const int xrow = tid >> 2;
    const int xq   = tid & 3;

    float acc[3][4][4] = {};
    float4 pxa, pxb;
    uint4 pw[6];

    {
        const float* s = &x[(size_t)(row0 + xrow) * CC + kbase + xq * 8];
        pxa = *reinterpret_cast<const float4*>(s);
        pxb = *reinterpret_cast<const float4*>(s + 4);
#pragma unroll
        for (int u = 0; u < 6; u++)
            pw[u] = g_wf[(u * 32 + gc0) * 256 + tid];
    }

    for (int c = 0; c < 16; c++) {
        if (c) __syncthreads();
        {
            float v[8] = {pxa.x, pxa.y, pxa.z, pxa.w, pxb.x, pxb.y, pxb.z, pxb.w};
            float h[8], l[8];
#pragma unroll
            for (int e = 0; e < 8; e++) {
                h[e] = bfhi(v[e]);
                l[e] = v[e] - h[e];
            }
            *reinterpret_cast<uint4*>(&Xh[xrow * 40 + xq * 8]) =
                make_uint4(bfpack(h[0], h[1]), bfpack(h[2], h[3]),
                           bfpack(h[4], h[5]), bfpack(h[6], h[7]));
            *reinterpret_cast<uint4*>(&Xl[xrow * 40 + xq * 8]) =
                make_uint4(bfpack(l[0], l[1]), bfpack(l[2], l[3]),
                           bfpack(l[4], l[5]), bfpack(l[6], l[7]));
#pragma unroll
            for (int u = 0; u < 6; u++)
                Wf[u * 256 + tid] = pw[u];
        }
        __syncthreads();

        if (c < 15) {
            const int kc = kbase + (c + 1) * 32;
            const float* s = &x[(size_t)(row0 + xrow) * CC + kc + xq * 8];
            pxa = *reinterpret_cast<const float4*>(s);
            pxb = *reinterpret_cast<const float4*>(s + 4);
#pragma unroll
            for (int u = 0; u < 6; u++)
                pw[u] = g_wf[(u * 32 + gc0 + c + 1) * 256 + tid];
        }

        u32 Ah[2][4], Al[2][4];
#pragma unroll
        for (int ks = 0; ks < 2; ks++) {
            int k0 = ks * 16;
            int r1 = (wm * 16 + lr) * 40, r2 = r1 + 8 * 40;
            Ah[ks][0] = *reinterpret_cast<u32*>(&Xh[r1 + k0 + lc2]);
            Ah[ks][1] = *reinterpret_cast<u32*>(&Xh[r2 + k0 + lc2]);
            Ah[ks][2] = *reinterpret_cast<u32*>(&Xh[r1 + k0 + lc2 + 8]);
            Ah[ks][3] = *reinterpret_cast<u32*>(&Xh[r2 + k0 + lc2 + 8]);
            Al[ks][0] = *reinterpret_cast<u32*>(&Xl[r1 + k0 + lc2]);
            Al[ks][1] = *reinterpret_cast<u32*>(&Xl[r2 + k0 + lc2]);
            Al[ks][2] = *reinterpret_cast<u32*>(&Xl[r1 + k0 + lc2 + 8]);
            Al[ks][3] = *reinterpret_cast<u32*>(&Xl[r2 + k0 + lc2 + 8]);
        }

#pragma unroll
        for (int mat = 0; mat < 3; mat++) {
#pragma unroll
            for (int nt = 0; nt < 4; nt++) {
                int fi = (wn * 4 + nt) * 32 + lane;
                uint4 BH = Wf[(mat * 2 + 0) * 256 + fi];
                uint4 BL = Wf[(mat * 2 + 1) * 256 + fi];
                float* D = acc[mat][nt];
                mma16816(D, Ah[0], BH.x, BH.y);
                mma16816(D, Al[0], BH.x, BH.y);
                mma16816(D, Ah[0], BL.x, BL.y);
                mma16816(D, Ah[1], BH.z, BH.w);
                mma16816(D, Al[1], BH.z, BH.w);
                mma16816(D, Ah[1], BL.z, BL.w);
            }
        }
    }

#pragma unroll
    for (int mat = 0; mat < 3; mat++) {
        float* dst = (blockIdx.y == 0)
            ? ((mat == 0) ? g_q : (mat == 1) ? g_k : g_v)
            : &g_p2[(size_t)mat * BB * TT * HS];
#pragma unroll
        for (int nt = 0; nt < 4; nt++) {
            int col = wn * 32 + nt * 8 + lc2;
            size_t r = (size_t)(row0 + wm * 16 + lr);
            *reinterpret_cast<float2*>(&dst[r * HS + col]) =
                make_float2(acc[mat][nt][0], acc[mat][nt][1]);
            *reinterpret_cast<float2*>(&dst[(r + 8) * HS + col]) =
                make_float2(acc[mat][nt][2], acc[mat][nt][3]);
        }
    }
}

// ---------------------------------------------------------------------------
// Kernel 2: merge K-halves AND convert (unchanged from R14).
// ---------------------------------------------------------------------------
__global__ __launch_bounds__(256) void merge_kernel() {
    const int t = blockIdx.x * 256 + threadIdx.x;
    const int per = (BB * TT * HS) / 8;
    const int m = t / per;
    const int i = (t - m * per) * 8;
    const float* a = (m == 0) ? g_q : (m == 1) ? g_k : g_v;
    const float* p = &g_p2[(size_t)m * BB * TT * HS];

    float4 a0 = *reinterpret_cast<const float4*>(&a[i]);
    float4 a1 = *reinterpret_cast<const float4*>(&a[i + 4]);
    float4 b0 = *reinterpret_cast<const float4*>(&p[i]);
    float4 b1 = *reinterpret_cast<const float4*>(&p[i + 4]);
    float v[8] = {a0.x + b0.x, a0.y + b0.y, a0.z + b0.z, a0.w + b0.w,
                  a1.x + b1.x, a1.y + b1.y, a1.z + b1.z, a1.w + b1.w};

    if (m == 2) {
        *reinterpret_cast<float4*>(&g_v[i])     = make_float4(v[0], v[1], v[2], v[3]);
        *reinterpret_cast<float4*>(&g_v[i + 4]) = make_float4(v[4], v[5], v[6], v[7]);
        return;
    }
    if (m == 0) {
#pragma unroll
        for (int e = 0; e < 8; e++) v[e] *= SCALE;
    }
    float h[8], l[8];
#pragma unroll
    for (int e = 0; e < 8; e++) {
        h[e] = bfhi(v[e]);
        l[e] = v[e] - h[e];
    }
    __nv_bfloat16* dh = (m == 0) ? g_qh : g_kh;
    __nv_bfloat16* dl = (m == 0) ? g_ql : g_kl;
    *reinterpret_cast<uint4*>(&dh[i]) =
        make_uint4(bfpack(h[0], h[1]), bfpack(h[2], h[3]),
                   bfpack(h[4], h[5]), bfpack(h[6], h[7]));
    *reinterpret_cast<uint4*>(&dl[i]) =
        make_uint4(bfpack(l[0], l[1]), bfpack(l[2], l[3]),
                   bfpack(l[4], l[5]), bfpack(l[6], l[7]));
}

// ---------------------------------------------------------------------------
// Kernel 3: V -> transposed bf16 hi/lo (unchanged).
// ---------------------------------------------------------------------------
__global__ __launch_bounds__(256) void vtrans_kernel() {
    __shared__ float sm[32][33];
    const int tx = threadIdx.x & 31;
    const int ty = threadIdx.x >> 5;
    const int t0 = blockIdx.x * 32;
    const int d0 = blockIdx.y * 32;
    const int b  = blockIdx.z;

#pragma unroll
    for (int i = 0; i < 4; i++)
        sm[ty + 8 * i][tx] =
            g_v[((size_t)(b * TT + t0 + ty + 8 * i)) * HS + d0 + tx];
    __syncthreads();
#pragma unroll
    for (int i = 0; i < 4; i++) {
        int d = d0 + ty + 8 * i;
        float v = sm[tx][ty + 8 * i];
        __nv_bfloat16 h = __float2bfloat16_rn(v);
        float lo = v - __bfloat162float(h);
        size_t a = ((size_t)b * HS + d) * TT + t0 + tx;
        g_vth[a] = h;
        g_vtl[a] = __float2bfloat16_rn(lo);
    }
}

// ---------------------------------------------------------------------------
// Kernel 4: flash-attention partials via mma.sync bf16x3 (R13 WIN, unchanged).
// ---------------------------------------------------------------------------
#define APITCH 72
__global__ __launch_bounds__(128) void attn_mma_kernel() {
    const int qtile = blockIdx.x;
    const int split = blockIdx.y;
    const int b     = blockIdx.z;

    const int tid  = threadIdx.x;
    const int warp = tid >> 5;
    const int lane = tid & 31;
    const int lr   = lane >> 2;
    const int lq2  = (lane & 3) * 2;
    const int q0   = qtile * 64;
    const int r_a  = warp * 16 + lr;

    __shared__ __align__(16) __nv_bfloat16 Ksm[2][64 * APITCH];
    __shared__ __align__(16) __nv_bfloat16 Vsm[2][64 * APITCH];

    u32 qh[4][4], ql[4][4];
    {
        size_t ra = (size_t)(b * TT + q0 + r_a) * HS;
        size_t rb = ra + 8 * HS;
#pragma unroll
        for (int ks = 0; ks < 4; ks++) {
            int o = ks * 16 + lq2;
            qh[ks][0] = *reinterpret_cast<const u32*>(&g_qh[ra + o]);
            qh[ks][1] = *reinterpret_cast<const u32*>(&g_qh[rb + o]);
            qh[ks][2] = *reinterpret_cast<const u32*>(&g_qh[ra + o + 8]);
            qh[ks][3] = *reinterpret_cast<const u32*>(&g_qh[rb + o + 8]);
            ql[ks][0] = *reinterpret_cast<const u32*>(&g_ql[ra + o]);
            ql[ks][1] = *reinterpret_cast<const u32*>(&g_ql[rb + o]);
            ql[ks][2] = *reinterpret_cast<const u32*>(&g_ql[ra + o + 8]);
            ql[ks][3] = *reinterpret_cast<const u32*>(&g_ql[rb + o + 8]);
        }
    }

    float O[8][4] = {};
    float m_a = -1e30f, m_b = -1e30f, l_a = 0.f, l_b = 0.f;

    for (int kt = split; kt <= qtile; kt += KSPLIT) {
        const int k0 = kt * 64;
        __syncthreads();
#pragma unroll
        for (int u = 0; u < 4; u++) {
            int lin = u * 128 + tid;
            int row = lin >> 3;
            int g   = lin & 7;
            size_t kb = ((size_t)(b * TT + k0 + row)) * HS + g * 8;
            size_t vb = ((size_t)b * HS + row) * TT + k0 + g * 8;
            *reinterpret_cast<uint4*>(&Ksm[0][row * APITCH + g * 8]) =
                *reinterpret_cast<const uint4*>(&g_kh[kb]);
            *reinterpret_cast<uint4*>(&Ksm[1][row * APITCH + g * 8]) =
                *reinterpret_cast<const uint4*>(&g_kl[kb]);
            *reinterpret_cast<uint4*>(&Vsm[0][row * APITCH + g * 8]) =
                *reinterpret_cast<const uint4*>(&g_vth[vb]);
            *reinterpret_cast<uint4*>(&Vsm[1][row * APITCH + g * 8]) =
                *reinterpret_cast<const uint4*>(&g_vtl[vb]);
        }
        __syncthreads();

        float D[8][4] = {};
#pragma unroll
        for (int ks = 0; ks < 4; ks++) {
            int ko = ks * 16 + lq2;
#pragma unroll
            for (int nt = 0; nt < 8; nt++) {
                int nr = (nt * 8 + lr) * APITCH + ko;
                u32 bh0 = *reinterpret_cast<u32*>(&Ksm[0][nr]);
                u32 bh1 = *reinterpret_cast<u32*>(&Ksm[0][nr + 8]);
                u32 bl0 = *reinterpret_cast<u32*>(&Ksm[1][nr]);
                u32 bl1 = *reinterpret_cast<u32*>(&Ksm[1][nr + 8]);
                mma16816(D[nt], qh[ks], bh0, bh1);
                mma16816(D[nt], ql[ks], bh0, bh1);
                mma16816(D[nt], qh[ks], bl0, bl1);
            }
        }

        if (kt == qtile) {
#pragma unroll
            for (int nt = 0; nt < 8; nt++) {
#pragma unroll
                for (int j = 0; j < 2; j++) {
                    int col = nt * 8 + lq2 + j;
                    if (col > r_a)     D[nt][j]     = -1e30f;
                    if (col > r_a + 8) D[nt][2 + j] = -1e30f;
                }
            }
        }

        float tm_a = -1e30f, tm_b = -1e30f;
#pragma unroll
        for (int nt = 0; nt < 8; nt++) {
            tm_a = fmaxf(tm_a, fmaxf(D[nt][0], D[nt][1]));
            tm_b = fmaxf(tm_b, fmaxf(D[nt][2], D[nt][3]));
        }
#pragma unroll
        for (int o = 1; o < 4; o <<= 1) {
            tm_a = fmaxf(tm_a, __shfl_xor_sync(0xffffffffu, tm_a, o));
            tm_b = fmaxf(tm_b, __shfl_xor_sync(0xffffffffu, tm_b, o));
        }
        float nm_a = fmaxf(m_a, tm_a), nm_b = fmaxf(m_b, tm_b);
        float cor_a = __expf(m_a - nm_a), cor_b = __expf(m_b - nm_b);
        float rs_a = 0.f, rs_b = 0.f;
#pragma unroll
        for (int nt = 0; nt < 8; nt++) {
            D[nt][0] = __expf(D[nt][0] - nm_a);
            D[nt][1] = __expf(D[nt][1] - nm_a);
            D[nt][2] = __expf(D[nt][2] - nm_b);
            D[nt][3] = __expf(D[nt][3] - nm_b);
            rs_a += D[nt][0] + D[nt][1];
            rs_b += D[nt][2] + D[nt][3];
        }
#pragma unroll
        for (int o = 1; o < 4; o <<= 1) {
            rs_a += __shfl_xor_sync(0xffffffffu, rs_a, o);
            rs_b += __shfl_xor_sync(0xffffffffu, rs_b, o);
        }
        l_a = l_a * cor_a + rs_a;  m_a = nm_a;
        l_b = l_b * cor_b + rs_b;  m_b = nm_b;
#pragma unroll
        for (int nt = 0; nt < 8; nt++) {
            O[nt][0] *= cor_a; O[nt][1] *= cor_a;
            O[nt][2] *= cor_b; O[nt][3] *= cor_b;
        }

#pragma unroll
        for (int ks = 0; ks < 4; ks++) {
            float h00 = bfhi(D[2*ks][0]),   l00 = D[2*ks][0]   - h00;
            float h01 = bfhi(D[2*ks][1]),   l01 = D[2*ks][1]   - h01;
            float h02 = bfhi(D[2*ks][2]),   l02 = D[2*ks][2]   - h02;
            float h03 = bfhi(D[2*ks][3]),   l03 = D[2*ks][3]   - h03;
            float h10 = bfhi(D[2*ks+1][0]), l10 = D[2*ks+1][0] - h10;
            float h11 = bfhi(D[2*ks+1][1]), l11 = D[2*ks+1][1] - h11;
            float h12 = bfhi(D[2*ks+1][2]), l12 = D[2*ks+1][2] - h12;
            float h13 = bfhi(D[2*ks+1][3]), l13 = D[2*ks+1][3] - h13;
            u32 PH[4] = {bfpack(h00, h01), bfpack(h02, h03),
                         bfpack(h10, h11), bfpack(h12, h13)};
            u32 PL[4] = {bfpack(l00, l01), bfpack(l02, l03),
                         bfpack(l10, l11), bfpack(l12, l13)};
            int ko = ks * 16 + lq2;
#pragma unroll
            for (int nt = 0; nt < 8; nt++) {
                int nr = (nt * 8 + lr) * APITCH + ko;
                u32 bh0 = *reinterpret_cast<u32*>(&Vsm[0][nr]);
                u32 bh1 = *reinterpret_cast<u32*>(&Vsm[0][nr + 8]);
                u32 bl0 = *reinterpret_cast<u32*>(&Vsm[1][nr]);
                u32 bl1 = *reinterpret_cast<u32*>(&Vsm[1][nr + 8]);
                mma16816(O[nt], PH, bh0, bh1);
                mma16816(O[nt], PL, bh0, bh1);
                mma16816(O[nt], PH, bl0, bl1);
            }
        }
    }

    const size_t base = (size_t)(b * KSPLIT + split) * TT + q0;
#pragma unroll
    for (int nt = 0; nt < 8; nt++) {
        int col = nt * 8 + lq2;
        *reinterpret_cast<float2*>(&g_pacc[(base + r_a) * HS + col]) =
            make_float2(O[nt][0], O[nt][1]);
        *reinterpret_cast<float2*>(&g_pacc[(base + r_a + 8) * HS + col]) =
            make_float2(O[nt][2], O[nt][3]);
    }
    if ((lane & 3) == 0) {
        g_pm[base + r_a] = m_a;     g_pl[base + r_a] = l_a;
        g_pm[base + r_a + 8] = m_b; g_pl[base + r_a + 8] = l_b;
    }
}

// ---------------------------------------------------------------------------
// Kernel 5: combine split partials — vectorized (float4 per thread).
// ---------------------------------------------------------------------------
__global__ __launch_bounds__(256) void combine_kernel(float* __restrict__ out) {
    const int t   = blockIdx.x * 256 + threadIdx.x;  // 0 .. B*T*HS/4-1
    const int d4  = t & 15;            // float4 group within row
    const int row = t >> 4;            // b*T + q
    const int b   = row >> 11;
    const int q   = row & (TT - 1);

    float M = -1e30f;
#pragma unroll
    for (int s = 0; s < KSPLIT; s++)
        M = fmaxf(M, g_pm[(size_t)(b * KSPLIT + s) * TT + q]);

    float L = 0.f;
    float4 A = make_float4(0.f, 0.f, 0.f, 0.f);
#pragma unroll
    for (int s = 0; s < KSPLIT; s++) {
        size_t pb = (size_t)(b * KSPLIT + s) * TT + q;
        float w = __expf(g_pm[pb] - M);
        L += g_pl[pb] * w;
        float4 p = *reinterpret_cast<const float4*>(&g_pacc[pb * HS + d4 * 4]);
        A.x += p.x * w; A.y += p.y * w; A.z += p.z * w; A.w += p.w * w;
    }
    float inv = 1.f / L;
    *reinterpret_cast<float4*>(&out[(size_t)row * HS + d4 * 4]) =
        make_float4(A.x * inv, A.y * inv, A.z * inv, A.w * inv);
}

// ---------------------------------------------------------------------------
extern "C" void kernel_launch(void* const* d_in, const int* in_sizes, int n_in,
                              void* d_out, int out_size) {
    const float* x  = (const float*)d_in[0];
    const float* Wq = (const float*)d_in[1];
    const float* Wk = (const float*)d_in[2];
    const float* Wv = (const float*)d_in[3];
    float* out = (float*)d_out;

    wconvert_kernel<<<(3 * 32 * 8 * 32) / 256, 256>>>(Wq, Wk, Wv);
    qkv_mma_kernel<<<dim3((BB * TT) / 64, 2), 256>>>(x);
    merge_kernel<<<(3 * BB * TT * HS / 8) / 256, 256>>>();
    vtrans_kernel<<<dim3(TT / 32, HS / 32, BB), 256>>>();
    attn_mma_kernel<<<dim3(TT / 64, KSPLIT, BB), 128>>>();
    combine_kernel<<<(BB * TT * HS / 4) / 256, 256>>>(out);
}

// round 17
// speedup vs baseline: 2.4055x; 1.0569x over previous
#include <cuda_runtime.h>
#include <cuda_bf16.h>

#define BB 4
#define TT 2048
#define CC 1024
#define HS 64
#define KSPLIT 8
#define SCALE 0.03125f   // C^-0.5 = 1024^-0.5

typedef unsigned long long u64;
typedef unsigned int u32;

// ---- warp-level HMMA: D[16x8] += A[16x16] * B[16x8]  (bf16 in, f32 acc) ----
__device__ __forceinline__ void mma16816(float* d, const u32* a, u32 b0, u32 b1) {
    asm volatile(
        "mma.sync.aligned.m16n8k16.row.col.f32.bf16.bf16.f32 "
        "{%0,%1,%2,%3},{%4,%5,%6,%7},{%8,%9},{%0,%1,%2,%3};"
        : "+f"(d[0]), "+f"(d[1]), "+f"(d[2]), "+f"(d[3])
        : "r"(a[0]), "r"(a[1]), "r"(a[2]), "r"(a[3]), "r"(b0), "r"(b1));
}
// ---- ldmatrix x4, non-transposed / transposed -------------------------------
__device__ __forceinline__ void ldsm4(u32& r0, u32& r1, u32& r2, u32& r3, u32 a) {
    asm volatile("ldmatrix.sync.aligned.m8n8.x4.shared.b16 {%0,%1,%2,%3},[%4];"
                 : "=r"(r0), "=r"(r1), "=r"(r2), "=r"(r3) : "r"(a));
}
__device__ __forceinline__ void ldsm4t(u32& r0, u32& r1, u32& r2, u32& r3, u32 a) {
    asm volatile("ldmatrix.sync.aligned.m8n8.x4.trans.shared.b16 {%0,%1,%2,%3},[%4];"
                 : "=r"(r0), "=r"(r1), "=r"(r2), "=r"(r3) : "r"(a));
}

__device__ __forceinline__ u32 bfpack(float a, float b) {
    __nv_bfloat162 t = __floats2bfloat162_rn(a, b);
    return *reinterpret_cast<u32*>(&t);
}
__device__ __forceinline__ float bfhi(float v) {
    return __bfloat162float(__float2bfloat16_rn(v));
}

// Scratch (static device allocations; no cudaMalloc allowed)
__device__ float g_q[BB * TT * HS];
__device__ float g_k[BB * TT * HS];
__device__ float g_v[BB * TT * HS];
__device__ float g_p2[3 * BB * TT * HS];    // qkv K-split half-1 partials
__device__ float g_pacc[(size_t)BB * KSPLIT * TT * HS];
__device__ float g_pm[BB * KSPLIT * TT];
__device__ float g_pl[BB * KSPLIT * TT];
// W in fragment-major layout: [mp=mat*2+part][chunk 0..31][nt 0..7][lane 0..31]
__device__ __align__(16) uint4 g_wf[6 * 32 * 8 * 32];
// attention operands, bf16 hi/lo (all natural [b][t][d])
__device__ __align__(16) __nv_bfloat16 g_qh[BB * TT * HS];  // pre-scaled
__device__ __align__(16) __nv_bfloat16 g_ql[BB * TT * HS];
__device__ __align__(16) __nv_bfloat16 g_kh[BB * TT * HS];
__device__ __align__(16) __nv_bfloat16 g_kl[BB * TT * HS];
__device__ __align__(16) __nv_bfloat16 g_vh[BB * TT * HS];
__device__ __align__(16) __nv_bfloat16 g_vl[BB * TT * HS];

// ---------------------------------------------------------------------------
// Kernel 0: W -> fragment-major bf16 hi/lo (unchanged R15).
// ---------------------------------------------------------------------------
__global__ __launch_bounds__(256) void wconvert_kernel(
    const float* __restrict__ Wq,
    const float* __restrict__ Wk,
    const float* __restrict__ Wv) {
    int idx = blockIdx.x * 256 + threadIdx.x;
    int mat  = idx >> 13;
    int rem  = idx & 8191;
    int c    = rem >> 8;
    int r2   = rem & 255;
    int nt   = r2 >> 5;
    int lane = r2 & 31;
    int lr   = lane >> 2;
    int lq2  = (lane & 3) * 2;
    int n    = nt * 8 + lr;
    int kc   = c * 32;
    const float* W = (mat == 0) ? Wq : (mat == 1) ? Wk : Wv;

    float h[8], l[8];
#pragma unroll
    for (int p = 0; p < 4; p++) {
        int k = kc + p * 8 + lq2;
        float v0 = W[(size_t)k * HS + n];
        float v1 = W[(size_t)(k + 1) * HS + n];
        h[p * 2]     = bfhi(v0);  l[p * 2]     = v0 - h[p * 2];
        h[p * 2 + 1] = bfhi(v1);  l[p * 2 + 1] = v1 - h[p * 2 + 1];
    }
    uint4 hv = make_uint4(bfpack(h[0], h[1]), bfpack(h[2], h[3]),
                          bfpack(h[4], h[5]), bfpack(h[6], h[7]));
    uint4 lv = make_uint4(bfpack(l[0], l[1]), bfpack(l[2], l[3]),
                          bfpack(l[4], l[5]), bfpack(l[6], l[7]));
    g_wf[(((mat * 2 + 0) * 32 + c) * 8 + nt) * 32 + lane] = hv;
    g_wf[(((mat * 2 + 1) * 32 + c) * 8 + nt) * 32 + lane] = lv;
}

// ---------------------------------------------------------------------------
// Kernel 1: QKV via mma.sync bf16x3, K-split (unchanged R15).
// ---------------------------------------------------------------------------
__global__ __launch_bounds__(256) void qkv_mma_kernel(const float* __restrict__ x) {
    __shared__ __align__(16) __nv_bfloat16 Xh[64 * 40];
    __shared__ __align__(16) __nv_bfloat16 Xl[64 * 40];
    __shared__ __align__(16) uint4 Wf[6 * 256];

    const int tid  = threadIdx.x;
    const int warp = tid >> 5;
    const int lane = tid & 31;
    const int wm = warp & 3;
    const int wn = warp >> 2;
    const int lr  = lane >> 2;
    const int lc2 = (lane & 3) * 2;
    const int row0 = blockIdx.x * 64;
    const int kbase = blockIdx.y * (CC / 2);
    const int gc0   = blockIdx.y * 16;

    const int xrow = tid >> 2;
    const int xq   = tid & 3;

    float acc[3][4][4] = {};
    float4 pxa, pxb;
    uint4 pw[6];

    {
        const float* s = &x[(size_t)(row0 + xrow) * CC + kbase + xq * 8];
        pxa = *reinterpret_cast<const float4*>(s);
        pxb = *reinterpret_cast<const float4*>(s + 4);
#pragma unroll
        for (int u = 0; u < 6; u++)
            pw[u] = g_wf[(u * 32 + gc0) * 256 + tid];
    }

    for (int c = 0; c < 16; c++) {
        if (c) __syncthreads();
        {
            float v[8] = {pxa.x, pxa.y, pxa.z, pxa.w, pxb.x, pxb.y, pxb.z, pxb.w};
            float h[8], l[8];
#pragma unroll
            for (int e = 0; e < 8; e++) {
                h[e] = bfhi(v[e]);
                l[e] = v[e] - h[e];
            }
            *reinterpret_cast<uint4*>(&Xh[xrow * 40 + xq * 8]) =
                make_uint4(bfpack(h[0], h[1]), bfpack(h[2], h[3]),
                           bfpack(h[4], h[5]), bfpack(h[6], h[7]));
            *reinterpret_cast<uint4*>(&Xl[xrow * 40 + xq * 8]) =
                make_uint4(bfpack(l[0], l[1]), bfpack(l[2], l[3]),
                           bfpack(l[4], l[5]), bfpack(l[6], l[7]));
#pragma unroll
            for (int u = 0; u < 6; u++)
                Wf[u * 256 + tid] = pw[u];
        }
        __syncthreads();

        if (c < 15) {
            const int kc = kbase + (c + 1) * 32;
            const float* s = &x[(size_t)(row0 + xrow) * CC + kc + xq * 8];
            pxa = *reinterpret_cast<const float4*>(s);
            pxb = *reinterpret_cast<const float4*>(s + 4);
#pragma unroll
            for (int u = 0; u < 6; u++)
                pw[u] = g_wf[(u * 32 + gc0 + c + 1) * 256 + tid];
        }

        u32 Ah[2][4], Al[2][4];
#pragma unroll
        for (int ks = 0; ks < 2; ks++) {
            int k0 = ks * 16;
            int r1 = (wm * 16 + lr) * 40, r2 = r1 + 8 * 40;
            Ah[ks][0] = *reinterpret_cast<u32*>(&Xh[r1 + k0 + lc2]);
            Ah[ks][1] = *reinterpret_cast<u32*>(&Xh[r2 + k0 + lc2]);
            Ah[ks][2] = *reinterpret_cast<u32*>(&Xh[r1 + k0 + lc2 + 8]);
            Ah[ks][3] = *reinterpret_cast<u32*>(&Xh[r2 + k0 + lc2 + 8]);
            Al[ks][0] = *reinterpret_cast<u32*>(&Xl[r1 + k0 + lc2]);
            Al[ks][1] = *reinterpret_cast<u32*>(&Xl[r2 + k0 + lc2]);
            Al[ks][2] = *reinterpret_cast<u32*>(&Xl[r1 + k0 + lc2 + 8]);
            Al[ks][3] = *reinterpret_cast<u32*>(&Xl[r2 + k0 + lc2 + 8]);
        }

#pragma unroll
        for (int mat = 0; mat < 3; mat++) {
#pragma unroll
            for (int nt = 0; nt < 4; nt++) {
                int fi = (wn * 4 + nt) * 32 + lane;
                uint4 BH = Wf[(mat * 2 + 0) * 256 + fi];
                uint4 BL = Wf[(mat * 2 + 1) * 256 + fi];
                float* D = acc[mat][nt];
                mma16816(D, Ah[0], BH.x, BH.y);
                mma16816(D, Al[0], BH.x, BH.y);
                mma16816(D, Ah[0], BL.x, BL.y);
                mma16816(D, Ah[1], BH.z, BH.w);
                mma16816(D, Al[1], BH.z, BH.w);
                mma16816(D, Ah[1], BL.z, BL.w);
            }
        }
    }

#pragma unroll
    for (int mat = 0; mat < 3; mat++) {
        float* dst = (blockIdx.y == 0)
            ? ((mat == 0) ? g_q : (mat == 1) ? g_k : g_v)
            : &g_p2[(size_t)mat * BB * TT * HS];
#pragma unroll
        for (int nt = 0; nt < 4; nt++) {
            int col = wn * 32 + nt * 8 + lc2;
            size_t r = (size_t)(row0 + wm * 16 + lr);
            *reinterpret_cast<float2*>(&dst[r * HS + col]) =
                make_float2(acc[mat][nt][0], acc[mat][nt][1]);
            *reinterpret_cast<float2*>(&dst[(r + 8) * HS + col]) =
                make_float2(acc[mat][nt][2], acc[mat][nt][3]);
        }
    }
}

// ---------------------------------------------------------------------------
// Kernel 2: merge K-halves and split Q/K/V to bf16 hi/lo (V now natural too).
// ---------------------------------------------------------------------------
__global__ __launch_bounds__(256) void merge_kernel() {
    const int t = blockIdx.x * 256 + threadIdx.x;
    const int per = (BB * TT * HS) / 8;
    const int m = t / per;
    const int i = (t - m * per) * 8;
    const float* a = (m == 0) ? g_q : (m == 1) ? g_k : g_v;
    const float* p = &g_p2[(size_t)m * BB * TT * HS];

    float4 a0 = *reinterpret_cast<const float4*>(&a[i]);
    float4 a1 = *reinterpret_cast<const float4*>(&a[i + 4]);
    float4 b0 = *reinterpret_cast<const float4*>(&p[i]);
    float4 b1 = *reinterpret_cast<const float4*>(&p[i + 4]);
    float v[8] = {a0.x + b0.x, a0.y + b0.y, a0.z + b0.z, a0.w + b0.w,
                  a1.x + b1.x, a1.y + b1.y, a1.z + b1.z, a1.w + b1.w};

    if (m == 0) {
#pragma unroll
        for (int e = 0; e < 8; e++) v[e] *= SCALE;
    }
    float h[8], l[8];
#pragma unroll
    for (int e = 0; e < 8; e++) {
        h[e] = bfhi(v[e]);
        l[e] = v[e] - h[e];
    }
    __nv_bfloat16* dh = (m == 0) ? g_qh : (m == 1) ? g_kh : g_vh;
    __nv_bfloat16* dl = (m == 0) ? g_ql : (m == 1) ? g_kl : g_vl;
    *reinterpret_cast<uint4*>(&dh[i]) =
        make_uint4(bfpack(h[0], h[1]), bfpack(h[2], h[3]),
                   bfpack(h[4], h[5]), bfpack(h[6], h[7]));
    *reinterpret_cast<uint4*>(&dl[i]) =
        make_uint4(bfpack(l[0], l[1]), bfpack(l[2], l[3]),
                   bfpack(l[4], l[5]), bfpack(l[6], l[7]));
}

// ---------------------------------------------------------------------------
// Kernel 3: flash-attention partials; B-fragments via ldmatrix (K non-trans,
// V trans — vtrans kernel eliminated).
// grid = (32 q-tiles, KSPLIT, 4 batches), 128 threads.
// ---------------------------------------------------------------------------
#define APITCH 72
__global__ __launch_bounds__(128) void attn_mma_kernel() {
    const int qtile = blockIdx.x;
    const int split = blockIdx.y;
    const int b     = blockIdx.z;

    const int tid  = threadIdx.x;
    const int warp = tid >> 5;
    const int lane = tid & 31;
    const int lr   = lane >> 2;
    const int lq2  = (lane & 3) * 2;
    const int sel  = lane >> 3;          // 0..3  ldmatrix tile select
    const int g8   = lane & 7;           // row within 8x8 tile
    const int q0   = qtile * 64;
    const int r_a  = warp * 16 + lr;

    __shared__ __align__(16) __nv_bfloat16 Ksm[2][64 * APITCH];  // hi/lo [key][dim]
    __shared__ __align__(16) __nv_bfloat16 Vsm[2][64 * APITCH];  // hi/lo [key][dim]

    // smem u32 bases for ldmatrix
    const u32 kbH = (u32)__cvta_generic_to_shared(&Ksm[0][0]);
    const u32 kbL = (u32)__cvta_generic_to_shared(&Ksm[1][0]);
    const u32 vbH = (u32)__cvta_generic_to_shared(&Vsm[0][0]);
    const u32 vbL = (u32)__cvta_generic_to_shared(&Vsm[1][0]);
    // K (non-trans): row = (2ntp + sel>>1)*8 + g8 (key), col = ks*16 + (sel&1)*8
    const u32 kOfs = ((u32)(((sel >> 1) * 8 + g8) * APITCH + (sel & 1) * 8)) * 2;
    // V (trans): row = ks*16 + (sel&1)*8 + g8 (key), col = (2ntp + sel>>1)*8
    const u32 vOfs = ((u32)(((sel & 1) * 8 + g8) * APITCH + (sel >> 1) * 8)) * 2;

    // Q fragments (once per block, direct LDG)
    u32 qh[4][4], ql[4][4];
    {
        size_t ra = (size_t)(b * TT + q0 + r_a) * HS;
        size_t rb = ra + 8 * HS;
#pragma unroll
        for (int ks = 0; ks < 4; ks++) {
            int o = ks * 16 + lq2;
            qh[ks][0] = *reinterpret_cast<const u32*>(&g_qh[ra + o]);
            qh[ks][1] = *reinterpret_cast<const u32*>(&g_qh[rb + o]);
            qh[ks][2] = *reinterpret_cast<const u32*>(&g_qh[ra + o + 8]);
            qh[ks][3] = *reinterpret_cast<const u32*>(&g_qh[rb + o + 8]);
            ql[ks][0] = *reinterpret_cast<const u32*>(&g_ql[ra + o]);
            ql[ks][1] = *reinterpret_cast<const u32*>(&g_ql[rb + o]);
            ql[ks][2] = *reinterpret_cast<const u32*>(&g_ql[ra + o + 8]);
            ql[ks][3] = *reinterpret_cast<const u32*>(&g_ql[rb + o + 8]);
        }
    }

    float O[8][4] = {};
    float m_a = -1e30f, m_b = -1e30f, l_a = 0.f, l_b = 0.f;

    for (int kt = split; kt <= qtile; kt += KSPLIT) {
        const int k0 = kt * 64;
        __syncthreads();
#pragma unroll
        for (int u = 0; u < 4; u++) {
            int lin = u * 128 + tid;
            int row = lin >> 3;
            int g   = lin & 7;
            size_t kb = ((size_t)(b * TT + k0 + row)) * HS + g * 8;
            *reinterpret_cast<uint4*>(&Ksm[0][row * APITCH + g * 8]) =
                *reinterpret_cast<const uint4*>(&g_kh[kb]);
            *reinterpret_cast<uint4*>(&Ksm[1][row * APITCH + g * 8]) =
                *reinterpret_cast<const uint4*>(&g_kl[kb]);
            *reinterpret_cast<uint4*>(&Vsm[0][row * APITCH + g * 8]) =
                *reinterpret_cast<const uint4*>(&g_vh[kb]);
            *reinterpret_cast<uint4*>(&Vsm[1][row * APITCH + g * 8]) =
                *reinterpret_cast<const uint4*>(&g_vl[kb]);
        }
        __syncthreads();

        // ---- S = Qs K^T  (ldmatrix non-trans for K fragments) ----
        float D[8][4] = {};
#pragma unroll
        for (int ks = 0; ks < 4; ks++) {
            const u32 colo = (u32)(ks * 16) * 2;
#pragma unroll
            for (int ntp = 0; ntp < 4; ntp++) {
                const u32 rowo = (u32)(ntp * 16 * APITCH) * 2;
                u32 h0, h1, h2, h3, l0, l1, l2, l3;
                ldsm4(h0, h1, h2, h3, kbH + rowo + colo + kOfs);
                ldsm4(l0, l1, l2, l3, kbL + rowo + colo + kOfs);
                mma16816(D[2 * ntp],     qh[ks], h0, h1);
                mma16816(D[2 * ntp],     ql[ks], h0, h1);
                mma16816(D[2 * ntp],     qh[ks], l0, l1);
                mma16816(D[2 * ntp + 1], qh[ks], h2, h3);
                mma16816(D[2 * ntp + 1], ql[ks], h2, h3);
                mma16816(D[2 * ntp + 1], qh[ks], l2, l3);
            }
        }

        // causal mask on the diagonal tile
        if (kt == qtile) {
#pragma unroll
            for (int nt = 0; nt < 8; nt++) {
#pragma unroll
                for (int j = 0; j < 2; j++) {
                    int col = nt * 8 + lq2 + j;
                    if (col > r_a)     D[nt][j]     = -1e30f;
                    if (col > r_a + 8) D[nt][2 + j] = -1e30f;
                }
            }
        }

        // ---- online softmax ----
        float tm_a = -1e30f, tm_b = -1e30f;
#pragma unroll
        for (int nt = 0; nt < 8; nt++) {
            tm_a = fmaxf(tm_a, fmaxf(D[nt][0], D[nt][1]));
            tm_b = fmaxf(tm_b, fmaxf(D[nt][2], D[nt][3]));
        }
#pragma unroll
        for (int o = 1; o < 4; o <<= 1) {
            tm_a = fmaxf(tm_a, __shfl_xor_sync(0xffffffffu, tm_a, o));
            tm_b = fmaxf(tm_b, __shfl_xor_sync(0xffffffffu, tm_b, o));
        }
        float nm_a = fmaxf(m_a, tm_a), nm_b = fmaxf(m_b, tm_b);
        float cor_a = __expf(m_a - nm_a), cor_b = __expf(m_b - nm_b);
        float rs_a = 0.f, rs_b = 0.f;
#pragma unroll
        for (int nt = 0; nt < 8; nt++) {
            D[nt][0] = __expf(D[nt][0] - nm_a);
            D[nt][1] = __expf(D[nt][1] - nm_a);
            D[nt][2] = __expf(D[nt][2] - nm_b);
            D[nt][3] = __expf(D[nt][3] - nm_b);
            rs_a += D[nt][0] + D[nt][1];
            rs_b += D[nt][2] + D[nt][3];
        }
#pragma unroll
        for (int o = 1; o < 4; o <<= 1) {
            rs_a += __shfl_xor_sync(0xffffffffu, rs_a, o);
            rs_b += __shfl_xor_sync(0xffffffffu, rs_b, o);
        }
        l_a = l_a * cor_a + rs_a;  m_a = nm_a;
        l_b = l_b * cor_b + rs_b;  m_b = nm_b;
#pragma unroll
        for (int nt = 0; nt < 8; nt++) {
            O[nt][0] *= cor_a; O[nt][1] *= cor_a;
            O[nt][2] *= cor_b; O[nt][3] *= cor_b;
        }

        // ---- O += P V  (ldmatrix.trans for V fragments) ----
#pragma unroll
        for (int ks = 0; ks < 4; ks++) {
            float h00 = bfhi(D[2*ks][0]),   l00 = D[2*ks][0]   - h00;
            float h01 = bfhi(D[2*ks][1]),   l01 = D[2*ks][1]   - h01;
            float h02 = bfhi(D[2*ks][2]),   l02 = D[2*ks][2]   - h02;
            float h03 = bfhi(D[2*ks][3]),   l03 = D[2*ks][3]   - h03;
            float h10 = bfhi(D[2*ks+1][0]), l10 = D[2*ks+1][0] - h10;
            float h11 = bfhi(D[2*ks+1][1]), l11 = D[2*ks+1][1] - h11;
            float h12 = bfhi(D[2*ks+1][2]), l12 = D[2*ks+1][2] - h12;
            float h13 = bfhi(D[2*ks+1][3]), l13 = D[2*ks+1][3] - h13;
            u32 PH[4] = {bfpack(h00, h01), bfpack(h02, h03),
                         bfpack(h10, h11), bfpack(h12, h13)};
            u32 PL[4] = {bfpack(l00, l01), bfpack(l02, l03),
                         bfpack(l10, l11), bfpack(l12, l13)};
            const u32 rowo = (u32)(ks * 16 * APITCH) * 2;
#pragma unroll
            for (int ntp = 0; ntp < 4; ntp++) {
                const u32 colo = (u32)(ntp * 16) * 2;
                u32 h0, h1, h2, h3, l0, l1, l2, l3;
                ldsm4t(h0, h1, h2, h3, vbH + rowo + colo + vOfs);
                ldsm4t(l0, l1, l2, l3, vbL + rowo + colo + vOfs);
                mma16816(O[2 * ntp],     PH, h0, h1);
                mma16816(O[2 * ntp],     PL, h0, h1);
                mma16816(O[2 * ntp],     PH, l0, l1);
                mma16816(O[2 * ntp + 1], PH, h2, h3);
                mma16816(O[2 * ntp + 1], PL, h2, h3);
                mma16816(O[2 * ntp + 1], PH, l2, l3);
            }
        }
    }

    // ---- write split partials ----
    const size_t base = (size_t)(b * KSPLIT + split) * TT + q0;
#pragma unroll
    for (int nt = 0; nt < 8; nt++) {
        int col = nt * 8 + lq2;
        *reinterpret_cast<float2*>(&g_pacc[(base + r_a) * HS + col]) =
            make_float2(O[nt][0], O[nt][1]);
        *reinterpret_cast<float2*>(&g_pacc[(base + r_a + 8) * HS + col]) =
            make_float2(O[nt][2], O[nt][3]);
    }
    if ((lane & 3) == 0) {
        g_pm[base + r_a] = m_a;     g_pl[base + r_a] = l_a;
        g_pm[base + r_a + 8] = m_b; g_pl[base + r_a + 8] = l_b;
    }
}

// ---------------------------------------------------------------------------
// Kernel 4: combine split partials — vectorized (unchanged R15).
// ---------------------------------------------------------------------------
__global__ __launch_bounds__(256) void combine_kernel(float* __restrict__ out) {
    const int t   = blockIdx.x * 256 + threadIdx.x;
    const int d4  = t & 15;
    const int row = t >> 4;
    const int b   = row >> 11;
    const int q   = row & (TT - 1);

    float M = -1e30f;
#pragma unroll
    for (int s = 0; s < KSPLIT; s++)
        M = fmaxf(M, g_pm[(size_t)(b * KSPLIT + s) * TT + q]);

    float L = 0.f;
    float4 A = make_float4(0.f, 0.f, 0.f, 0.f);
#pragma unroll
    for (int s = 0; s < KSPLIT; s++) {
        size_t pb = (size_t)(b * KSPLIT + s) * TT + q;
        float w = __expf(g_pm[pb] - M);
        L += g_pl[pb] * w;
        float4 p = *reinterpret_cast<const float4*>(&g_pacc[pb * HS + d4 * 4]);
        A.x += p.x * w; A.y += p.y * w; A.z += p.z * w; A.w += p.w * w;
    }
    float inv = 1.f / L;
    *reinterpret_cast<float4*>(&out[(size_t)row * HS + d4 * 4]) =
        make_float4(A.x * inv, A.y * inv, A.z * inv, A.w * inv);
}

// ---------------------------------------------------------------------------
extern "C" void kernel_launch(void* const* d_in, const int* in_sizes, int n_in,
                              void* d_out, int out_size) {
    const float* x  = (const float*)d_in[0];
    const float* Wq = (const float*)d_in[1];
    const float* Wk = (const float*)d_in[2];
    const float* Wv = (const float*)d_in[3];
    float* out = (float*)d_out;

    wconvert_kernel<<<(3 * 32 * 8 * 32) / 256, 256>>>(Wq, Wk, Wv);
    qkv_mma_kernel<<<dim3((BB * TT) / 64, 2), 256>>>(x);
    merge_kernel<<<(3 * BB * TT * HS / 8) / 256, 256>>>();
    attn_mma_kernel<<<dim3(TT / 64, KSPLIT, BB), 128>>>();
    combine_kernel<<<(BB * TT * HS / 4) / 256, 256>>>(out);
}